// round 13
// baseline (speedup 1.0000x reference)
#include <cuda_runtime.h>
#include <cuda_bf16.h>
#include <cuda_fp8.h>
#include <cstdint>

// Problem constants
#define T_DIM 1024
#define N_QK  256
#define N_V   256
#define C_DIM 128
#define BD    1024
#define M_TOT (BD * C_DIM)   // 131072

// ---------------------------------------------------------------------------
// Scratch (__device__ globals; alloc-free rule)
// ---------------------------------------------------------------------------
__device__ __align__(16) __nv_bfloat16 g_qh[(size_t)M_TOT * N_QK];
__device__ __align__(16) __nv_bfloat16 g_ql[(size_t)M_TOT * N_QK];
__device__ __align__(16) __nv_bfloat16 g_kh[(size_t)M_TOT * N_QK];
__device__ __align__(16) __nv_bfloat16 g_kl[(size_t)M_TOT * N_QK];
__device__ __align__(16) __nv_bfloat16 g_vh[(size_t)M_TOT * N_V];
__device__ __align__(16) __nv_bfloat16 g_vl[(size_t)M_TOT * N_V];

__device__ __align__(16) __nv_bfloat16 g_xh[(size_t)M_TOT * T_DIM];   // bf16 X
__device__ __align__(16) uint8_t g_xh8[(size_t)M_TOT * T_DIM];        // e4m3(x)
__device__ __align__(16) uint8_t g_xl8[(size_t)M_TOT * T_DIM];        // e4m3((x-xh)*128)
__device__ __align__(16) __nv_bfloat16 g_wh[3 * 256 * T_DIM];         // bf16 W
__device__ __align__(16) uint8_t g_wl8[3 * 256 * T_DIM];              // e4m3((w-wh)*2048)
__device__ __align__(16) uint8_t g_wh8[3 * 256 * T_DIM];              // e4m3(wh*16)

// ---------------------------------------------------------------------------
// Helpers
// ---------------------------------------------------------------------------
__device__ __forceinline__ uint32_t smem_u32(const void* p) {
    uint32_t a;
    asm("{ .reg .u64 t; cvta.to.shared.u64 t, %1; cvt.u32.u64 %0, t; }"
        : "=r"(a) : "l"(p));
    return a;
}
__device__ __forceinline__ void cp16(uint32_t dst, const void* src) {
    asm volatile("cp.async.cg.shared.global [%0], [%1], 16;"
                 :: "r"(dst), "l"(src) : "memory");
}
#define CP_COMMIT() asm volatile("cp.async.commit_group;" ::: "memory")
#define CP_WAIT1()  asm volatile("cp.async.wait_group 1;" ::: "memory")

__device__ __forceinline__ void ldsm4(uint32_t* r, uint32_t addr) {
    asm volatile("ldmatrix.sync.aligned.m8n8.x4.shared.b16 {%0,%1,%2,%3}, [%4];"
                 : "=r"(r[0]), "=r"(r[1]), "=r"(r[2]), "=r"(r[3]) : "r"(addr));
}
__device__ __forceinline__ void ldsm4t(uint32_t* r, uint32_t addr) {
    asm volatile("ldmatrix.sync.aligned.m8n8.x4.trans.shared.b16 {%0,%1,%2,%3}, [%4];"
                 : "=r"(r[0]), "=r"(r[1]), "=r"(r[2]), "=r"(r[3]) : "r"(addr));
}
__device__ __forceinline__ void mma16816(float* d, const uint32_t* a,
                                         uint32_t b0, uint32_t b1) {
    asm volatile(
        "mma.sync.aligned.m16n8k16.row.col.f32.bf16.bf16.f32 "
        "{%0,%1,%2,%3}, {%4,%5,%6,%7}, {%8,%9}, {%0,%1,%2,%3};"
        : "+f"(d[0]), "+f"(d[1]), "+f"(d[2]), "+f"(d[3])
        : "r"(a[0]), "r"(a[1]), "r"(a[2]), "r"(a[3]), "r"(b0), "r"(b1));
}
__device__ __forceinline__ void mma_fp8(float* d, const uint32_t* a,
                                        uint32_t b0, uint32_t b1) {
    asm volatile(
        "mma.sync.aligned.m16n8k32.row.col.f32.e4m3.e4m3.f32 "
        "{%0,%1,%2,%3}, {%4,%5,%6,%7}, {%8,%9}, {%0,%1,%2,%3};"
        : "+f"(d[0]), "+f"(d[1]), "+f"(d[2]), "+f"(d[3])
        : "r"(a[0]), "r"(a[1]), "r"(a[2]), "r"(a[3]), "r"(b0), "r"(b1));
}
__device__ __forceinline__ uint32_t pack_bf2(__nv_bfloat16 a, __nv_bfloat16 b) {
    return (uint32_t)__bfloat16_as_ushort(a) | ((uint32_t)__bfloat16_as_ushort(b) << 16);
}
__device__ __forceinline__ uint32_t pack_fp8x4(float a, float b, float c, float d) {
    __nv_fp8x2_storage_t lo = __nv_cvt_float2_to_fp8x2(make_float2(a, b),
                                                       __NV_SATFINITE, __NV_E4M3);
    __nv_fp8x2_storage_t hi = __nv_cvt_float2_to_fp8x2(make_float2(c, d),
                                                       __NV_SATFINITE, __NV_E4M3);
    return (uint32_t)lo | ((uint32_t)hi << 16);
}

// ---------------------------------------------------------------------------
// conv_x: x -> bf16 xh, e4m3 xh8 (=e4m3(x)), e4m3 xl8 (=(x-xh)*128)
// ---------------------------------------------------------------------------
__global__ void __launch_bounds__(256) conv_x(const float* __restrict__ x)
{
    const size_t n4 = (size_t)M_TOT * T_DIM / 4;
    const size_t stride = (size_t)gridDim.x * blockDim.x;
    uint2*    __restrict__ xh  = (uint2*)g_xh;
    uint32_t* __restrict__ xh8 = (uint32_t*)g_xh8;
    uint32_t* __restrict__ xl8 = (uint32_t*)g_xl8;
    for (size_t i = (size_t)blockIdx.x * blockDim.x + threadIdx.x; i < n4; i += stride) {
        float4 f = ((const float4*)x)[i];
        __nv_bfloat16 h0 = __float2bfloat16(f.x);
        __nv_bfloat16 h1 = __float2bfloat16(f.y);
        __nv_bfloat16 h2 = __float2bfloat16(f.z);
        __nv_bfloat16 h3 = __float2bfloat16(f.w);
        xh[i] = make_uint2(pack_bf2(h0, h1), pack_bf2(h2, h3));
        xh8[i] = pack_fp8x4(f.x, f.y, f.z, f.w);
        xl8[i] = pack_fp8x4((f.x - __bfloat162float(h0)) * 128.0f,
                            (f.y - __bfloat162float(h1)) * 128.0f,
                            (f.z - __bfloat162float(h2)) * 128.0f,
                            (f.w - __bfloat162float(h3)) * 128.0f);
    }
}

// ---------------------------------------------------------------------------
// conv_w: w -> bf16 wh, e4m3 wl8 (=(w-wh)*2048), e4m3 wh8 (=wh*16)
// ---------------------------------------------------------------------------
__global__ void __launch_bounds__(256) conv_w(const float* __restrict__ Wq,
                                              const float* __restrict__ Wk,
                                              const float* __restrict__ Wv)
{
    const int mat = blockIdx.y;
    const float* W = (mat == 0) ? Wq : (mat == 1) ? Wk : Wv;
    const size_t n4 = 256 * T_DIM / 4;
    const size_t base = (size_t)mat * n4;
    uint2*    __restrict__ wh  = (uint2*)g_wh;
    uint32_t* __restrict__ wl8 = (uint32_t*)g_wl8;
    uint32_t* __restrict__ wh8 = (uint32_t*)g_wh8;
    for (size_t i = (size_t)blockIdx.x * blockDim.x + threadIdx.x; i < n4;
         i += (size_t)gridDim.x * blockDim.x) {
        float4 f = ((const float4*)W)[i];
        __nv_bfloat16 h0 = __float2bfloat16(f.x);
        __nv_bfloat16 h1 = __float2bfloat16(f.y);
        __nv_bfloat16 h2 = __float2bfloat16(f.z);
        __nv_bfloat16 h3 = __float2bfloat16(f.w);
        float hf0 = __bfloat162float(h0), hf1 = __bfloat162float(h1);
        float hf2 = __bfloat162float(h2), hf3 = __bfloat162float(h3);
        wh[base + i] = make_uint2(pack_bf2(h0, h1), pack_bf2(h2, h3));
        wl8[base + i] = pack_fp8x4((f.x - hf0) * 2048.0f, (f.y - hf1) * 2048.0f,
                                   (f.z - hf2) * 2048.0f, (f.w - hf3) * 2048.0f);
        wh8[base + i] = pack_fp8x4(hf0 * 16.0f, hf1 * 16.0f,
                                   hf2 * 16.0f, hf3 * 16.0f);
    }
}

// ---------------------------------------------------------------------------
// GEMM: 128x128 CTA tile, 256 thr (8 warps 2x4), 64x32 warp tile, 2 CTA/SM.
// Loop A (fp8 corrections, BK=64, 16 chunks):
//   acc += e4m3(X) @ e4m3(Wl*2^11)  +  e4m3(Xl*2^7) @ e4m3(Wh*2^4)
// rescale acc *= 2^-11, then
// Loop B (bf16 main, BK=64, 16 chunks): acc += Xh @ Wh
// Epilogue: bias add, split to bf16 hi/lo.
// ---------------------------------------------------------------------------
// Loop A smem (pitch 80, 64B data): 4 tiles
#define A8H 0
#define A8L 10240
#define B8L 20480
#define B8H 30720
#define A_STAGE 40960
// Loop B smem (pitch 144, 128B data): 2 tiles
#define BAH 0
#define BBH 18432
#define B_STAGE 36864
#define GEMM_SMEM (2 * A_STAGE)   // 81920 (loop B fits inside)
#define NCH_A 16
#define NCH_B 16

__device__ __forceinline__ void load_a8(
    uint32_t st, const uint8_t* __restrict__ xh8,
    const uint8_t* __restrict__ xl8,
    const uint8_t* __restrict__ wl8,
    const uint8_t* __restrict__ wh8, int k0, int tid)
{
#pragma unroll
    for (int t = 0; t < 2; t++) {
        int op = tid + t * 256;        // 0..511
        int r  = op >> 2;              // 0..127
        int sg = op & 3;               // 16B segs of 64B row
        uint32_t doff = (uint32_t)(r * 80 + sg * 16);
        size_t soff = (size_t)r * T_DIM + k0 + sg * 16;
        cp16(st + A8H + doff, xh8 + soff);
        cp16(st + A8L + doff, xl8 + soff);
        cp16(st + B8L + doff, wl8 + soff);
        cp16(st + B8H + doff, wh8 + soff);
    }
}

__device__ __forceinline__ void load_bf(
    uint32_t st, const __nv_bfloat16* __restrict__ xh,
    const __nv_bfloat16* __restrict__ wh, int k0, int tid)
{
#pragma unroll
    for (int t = 0; t < 4; t++) {
        int op = tid + t * 256;        // 0..1023
        int r  = op >> 3;              // 0..127
        int sg = op & 7;               // 16B segs of 128B row
        uint32_t doff = (uint32_t)(r * 144 + sg * 16);
        size_t soff = (size_t)r * T_DIM + k0 + sg * 8;
        cp16(st + BAH + doff, xh + soff);
        cp16(st + BBH + doff, wh + soff);
    }
}

__global__ void __launch_bounds__(256, 2) gemm_mma(
    const float* __restrict__ bq, const float* __restrict__ bk,
    const float* __restrict__ bv)
{
    extern __shared__ __align__(16) char dyn[];

    const int tid  = threadIdx.x;
    const int lane = tid & 31;
    const int wid  = tid >> 5;
    const int mat  = blockIdx.x >> 1;
    const int bn   = blockIdx.x & 1;
    const int bm   = blockIdx.y;

    const int wm = (wid >> 2) * 64;
    const int wn = (wid & 3) * 32;

    const uint8_t* xh8 = g_xh8 + (size_t)bm * 128 * T_DIM;
    const uint8_t* xl8 = g_xl8 + (size_t)bm * 128 * T_DIM;
    const __nv_bfloat16* xh = g_xh + (size_t)bm * 128 * T_DIM;
    const size_t wrow = ((size_t)mat * 256 + bn * 128) * T_DIM;
    const uint8_t* wl8 = g_wl8 + wrow;
    const uint8_t* wh8 = g_wh8 + wrow;
    const __nv_bfloat16* wh = g_wh + wrow;
    const float* bias = (mat == 0) ? bq : (mat == 1) ? bk : bv;
    __nv_bfloat16* outh = ((mat == 0) ? g_qh : (mat == 1) ? g_kh : g_vh)
                          + (size_t)bm * 128 * 256 + bn * 128;
    __nv_bfloat16* outl = ((mat == 0) ? g_ql : (mat == 1) ? g_kl : g_vl)
                          + (size_t)bm * 128 * 256 + bn * 128;

    const uint32_t sbase = smem_u32(dyn);

    float acc[4][4][4];
#pragma unroll
    for (int i = 0; i < 4; i++)
#pragma unroll
        for (int j = 0; j < 4; j++)
#pragma unroll
            for (int r = 0; r < 4; r++) acc[i][j][r] = 0.0f;

    // ============== Loop A: fp8 corrections ==============
    {
        const uint32_t aoff = (uint32_t)((wm + (lane & 15)) * 80 + (lane >> 4) * 16);
        const uint32_t boff = (uint32_t)((wn + ((lane >> 4) << 3) + (lane & 7)) * 80
                                         + ((lane >> 3) & 1) * 16);

        load_a8(sbase + 0 * A_STAGE, xh8, xl8, wl8, wh8, 0, tid);
        CP_COMMIT();
        load_a8(sbase + 1 * A_STAGE, xh8, xl8, wl8, wh8, 64, tid);
        CP_COMMIT();

        for (int c = 0; c < NCH_A; c++) {
            const uint32_t st = sbase + (c & 1) * A_STAGE;
            CP_WAIT1();
            __syncthreads();

#pragma unroll
            for (int g = 0; g < 2; g++) {
                const uint32_t kadd = (uint32_t)(g * 32);
                uint32_t a8[4][4], b8[2][4];
                // pass 1: e4m3(X) @ e4m3(Wl*2^11)
#pragma unroll
                for (int mi = 0; mi < 4; mi++)
                    ldsm4(a8[mi], st + A8H + aoff + mi * (16 * 80) + kadd);
#pragma unroll
                for (int np = 0; np < 2; np++)
                    ldsm4(b8[np], st + B8L + boff + np * (16 * 80) + kadd);
#pragma unroll
                for (int mi = 0; mi < 4; mi++)
#pragma unroll
                    for (int nj = 0; nj < 4; nj++)
                        mma_fp8(acc[mi][nj], a8[mi], b8[nj >> 1][(nj & 1) * 2],
                                b8[nj >> 1][(nj & 1) * 2 + 1]);
                // pass 2: e4m3(Xl*2^7) @ e4m3(Wh*2^4)
#pragma unroll
                for (int mi = 0; mi < 4; mi++)
                    ldsm4(a8[mi], st + A8L + aoff + mi * (16 * 80) + kadd);
#pragma unroll
                for (int np = 0; np < 2; np++)
                    ldsm4(b8[np], st + B8H + boff + np * (16 * 80) + kadd);
#pragma unroll
                for (int mi = 0; mi < 4; mi++)
#pragma unroll
                    for (int nj = 0; nj < 4; nj++)
                        mma_fp8(acc[mi][nj], a8[mi], b8[nj >> 1][(nj & 1) * 2],
                                b8[nj >> 1][(nj & 1) * 2 + 1]);
            }

            __syncthreads();
            if (c + 2 < NCH_A)
                load_a8(st, xh8, xl8, wl8, wh8, (c + 2) * 64, tid);
            CP_COMMIT();
        }
    }

    // rescale corrections (operand products carried 2^11)
    {
        const float rs = 1.0f / 2048.0f;
#pragma unroll
        for (int i = 0; i < 4; i++)
#pragma unroll
            for (int j = 0; j < 4; j++)
#pragma unroll
                for (int r = 0; r < 4; r++) acc[i][j][r] *= rs;
    }

    // ============== Loop B: bf16 main term ==============
    {
        const uint32_t aoff = (uint32_t)((wm + (lane & 15)) * 144 + (lane >> 4) * 16);
        const uint32_t boff = (uint32_t)((wn + ((lane >> 4) << 3) + (lane & 7)) * 144
                                         + ((lane >> 3) & 1) * 16);

        load_bf(sbase + 0 * B_STAGE, xh, wh, 0, tid);
        CP_COMMIT();
        load_bf(sbase + 1 * B_STAGE, xh, wh, 64, tid);
        CP_COMMIT();

        for (int c = 0; c < NCH_B; c++) {
            const uint32_t st = sbase + (c & 1) * B_STAGE;
            CP_WAIT1();
            __syncthreads();

#pragma unroll
            for (int ks = 0; ks < 4; ks++) {
                const uint32_t kadd = (uint32_t)(ks * 32);
                uint32_t ah[4][4], bh[2][4];
#pragma unroll
                for (int mi = 0; mi < 4; mi++)
                    ldsm4(ah[mi], st + BAH + aoff + mi * (16 * 144) + kadd);
#pragma unroll
                for (int np = 0; np < 2; np++)
                    ldsm4(bh[np], st + BBH + boff + np * (16 * 144) + kadd);
#pragma unroll
                for (int mi = 0; mi < 4; mi++)
#pragma unroll
                    for (int nj = 0; nj < 4; nj++)
                        mma16816(acc[mi][nj], ah[mi], bh[nj >> 1][(nj & 1) * 2],
                                 bh[nj >> 1][(nj & 1) * 2 + 1]);
            }

            __syncthreads();
            if (c + 2 < NCH_B)
                load_bf(st, xh, wh, (c + 2) * 64, tid);
            CP_COMMIT();
        }
    }

    // Epilogue: bias add, split to bf16 hi/lo, store both
    const int rq = lane >> 2;
    const int cq = (lane & 3) * 2;
#pragma unroll
    for (int nj = 0; nj < 4; nj++) {
        const int col = wn + nj * 8 + cq;
        const float b0 = bias[bn * 128 + col];
        const float b1 = bias[bn * 128 + col + 1];
#pragma unroll
        for (int mi = 0; mi < 4; mi++) {
            const int row = wm + mi * 16 + rq;
#pragma unroll
            for (int half = 0; half < 2; half++) {
                const float v0 = acc[mi][nj][half * 2 + 0] + b0;
                const float v1 = acc[mi][nj][half * 2 + 1] + b1;
                __nv_bfloat16 h0 = __float2bfloat16(v0);
                __nv_bfloat16 h1 = __float2bfloat16(v1);
                __nv_bfloat16 l0 = __float2bfloat16(v0 - __bfloat162float(h0));
                __nv_bfloat16 l1 = __float2bfloat16(v1 - __bfloat162float(h1));
                const size_t off = (size_t)(row + half * 8) * 256 + col;
                *(uint32_t*)(outh + off) = pack_bf2(h0, h1);
                *(uint32_t*)(outl + off) = pack_bf2(l0, l1);
            }
        }
    }
}

// ---------------------------------------------------------------------------
// Tensor-core attention (R10-exact): 2 CTAs/SM, register softmax,
// phase-2 in two 128-col halves.
// ---------------------------------------------------------------------------
#define P1_ROWB  80
#define P1_TILE  (128 * P1_ROWB)
#define P1_QH    0
#define P1_QL    (1 * P1_TILE)
#define P1_KH    (2 * P1_TILE)
#define P1_KL    (3 * P1_TILE)
#define P1_STAGE (4 * P1_TILE)          // 40960
#define R1_SIZE  (2 * P1_STAGE)         // 81920

#define S_PITCH  136
#define SH_OFF   0
#define SL_OFF   (128 * S_PITCH * 2)    // 34816

#define RB_OFF   R1_SIZE
#define BUFMAX_OFF RB_OFF
#define BUFSUM_OFF (RB_OFF + 2048)
#define V_OFF    (RB_OFF + 4096)
#define V2_PITCHB 272
#define V2_TILE  (16 * V2_PITCHB)       // 4352
#define V2_STAGE (2 * V2_TILE)          // 8704
#define ATTN_SMEM (V_OFF + 2 * V2_STAGE)   // 103424

__device__ __forceinline__ void p1_load(
    uint32_t st, const __nv_bfloat16* __restrict__ qh,
    const __nv_bfloat16* __restrict__ ql,
    const __nv_bfloat16* __restrict__ kh,
    const __nv_bfloat16* __restrict__ kl, int k0, int tid)
{
#pragma unroll
    for (int t = 0; t < 2; t++) {
        int op = tid + t * 256;
        int r  = op >> 2;
        int ch = op & 3;
        uint32_t doff = (uint32_t)(r * P1_ROWB + ch * 16);
        size_t soff = (size_t)r * N_QK + k0 + ch * 8;
        cp16(st + P1_QH + doff, qh + soff);
        cp16(st + P1_QL + doff, ql + soff);
        cp16(st + P1_KH + doff, kh + soff);
        cp16(st + P1_KL + doff, kl + soff);
    }
}

__device__ __forceinline__ void v_load2(
    uint32_t st, const __nv_bfloat16* __restrict__ vh,
    const __nv_bfloat16* __restrict__ vl, int k0, int h, int tid)
{
    int r  = tid >> 4;
    int ch = tid & 15;
    uint32_t doff = (uint32_t)(r * V2_PITCHB + ch * 16);
    size_t soff = (size_t)(k0 + r) * N_V + h * 128 + ch * 8;
    cp16(st + doff, vh + soff);
    cp16(st + V2_TILE + doff, vl + soff);
}

__global__ void __launch_bounds__(256, 2) attn_tc(float* __restrict__ out)
{
    extern __shared__ __align__(16) char dyn[];
    const uint32_t sb = smem_u32(dyn);

    const int tid  = threadIdx.x;
    const int lane = tid & 31;
    const int wid  = tid >> 5;
    const int bd   = blockIdx.x;

    const __nv_bfloat16* qh = g_qh + (size_t)bd * C_DIM * N_QK;
    const __nv_bfloat16* ql = g_ql + (size_t)bd * C_DIM * N_QK;
    const __nv_bfloat16* kh = g_kh + (size_t)bd * C_DIM * N_QK;
    const __nv_bfloat16* kl = g_kl + (size_t)bd * C_DIM * N_QK;
    const __nv_bfloat16* vh = g_vh + (size_t)bd * C_DIM * N_V;
    const __nv_bfloat16* vl = g_vl + (size_t)bd * C_DIM * N_V;
    float* ob = out + (size_t)bd * C_DIM * N_V;

    const int wm = (wid >> 2) * 64;
    const int wn = (wid & 3) * 32;
    const int rq = lane >> 2;
    const int cq = (lane & 3) * 2;

    float* bufMax = (float*)(dyn + BUFMAX_OFF);
    float* bufSum = (float*)(dyn + BUFSUM_OFF);

    // ================= Phase 1: S = q @ k^T (regs) =================
    float acc[4][4][4];
#pragma unroll
    for (int i = 0; i < 4; i++)
#pragma unroll
        for (int j = 0; j < 4; j++)
#pragma unroll
            for (int r = 0; r < 4; r++) acc[i][j][r] = 0.0f;

    {
        const uint32_t aoff = (uint32_t)((wm + (lane & 15)) * P1_ROWB + (lane >> 4) * 16);
        const uint32_t boff = (uint32_t)((wn + ((lane >> 4) << 3) + (lane & 7)) * P1_ROWB
                                         + ((lane >> 3) & 1) * 16);

        p1_load(sb + 0 * P1_STAGE, qh, ql, kh, kl, 0, tid);
        CP_COMMIT();
        p1_load(sb + 1 * P1_STAGE, qh, ql, kh, kl, 32, tid);
        CP_COMMIT();

        for (int c = 0; c < 8; c++) {
            const uint32_t st = sb + (c & 1) * P1_STAGE;
            CP_WAIT1();
            __syncthreads();

#pragma unroll
            for (int ks = 0; ks < 2; ks++) {
                const uint32_t kadd = (uint32_t)(ks * 32);
                uint32_t ah[4][4], bh[2][4];
#pragma unroll
                for (int mi = 0; mi < 4; mi++)
                    ldsm4(ah[mi], st + P1_QH + aoff + mi * (16 * P1_ROWB) + kadd);
#pragma unroll
                for (int np = 0; np < 2; np++)
                    ldsm4(bh[np], st + P1_KH + boff + np * (16 * P1_ROWB) + kadd);
#pragma unroll
                for (int mi = 0; mi < 4; mi++)
#pragma unroll
                    for (int nj = 0; nj < 4; nj++)
                        mma16816(acc[mi][nj], ah[mi], bh[nj >> 1][(nj & 1) * 2],
                                 bh[nj >> 1][(nj & 1) * 2 + 1]);

                uint32_t bl[2][4];
#pragma unroll
                for (int np = 0; np < 2; np++)
                    ldsm4(bl[np], st + P1_KL + boff + np * (16 * P1_ROWB) + kadd);
#pragma unroll
                for (int mi = 0; mi < 4; mi++)
#pragma unroll
                    for (int nj = 0; nj < 4; nj++)
                        mma16816(acc[mi][nj], ah[mi], bl[nj >> 1][(nj & 1) * 2],
                                 bl[nj >> 1][(nj & 1) * 2 + 1]);

                uint32_t al[4][4];
#pragma unroll
                for (int mi = 0; mi < 4; mi++)
                    ldsm4(al[mi], st + P1_QL + aoff + mi * (16 * P1_ROWB) + kadd);
#pragma unroll
                for (int mi = 0; mi < 4; mi++)
#pragma unroll
                    for (int nj = 0; nj < 4; nj++)
                        mma16816(acc[mi][nj], al[mi], bh[nj >> 1][(nj & 1) * 2],
                                 bh[nj >> 1][(nj & 1) * 2 + 1]);
            }

            __syncthreads();
            if (c + 2 < 8)
                p1_load(st, qh, ql, kh, kl, (c + 2) * 32, tid);
            CP_COMMIT();
        }
    }

    // ================= Softmax from registers =================
    {
        const float scale = 0.0625f;
#pragma unroll
        for (int mi = 0; mi < 4; mi++)
#pragma unroll
            for (int nj = 0; nj < 4; nj++)
#pragma unroll
                for (int r = 0; r < 4; r++) acc[mi][nj][r] *= scale;

        float m[4][2];
#pragma unroll
        for (int mi = 0; mi < 4; mi++)
#pragma unroll
            for (int h = 0; h < 2; h++) {
                float v = -1e30f;
#pragma unroll
                for (int nj = 0; nj < 4; nj++) {
                    v = fmaxf(v, acc[mi][nj][h * 2]);
                    v = fmaxf(v, acc[mi][nj][h * 2 + 1]);
                }
                v = fmaxf(v, __shfl_xor_sync(0xffffffffu, v, 1));
                v = fmaxf(v, __shfl_xor_sync(0xffffffffu, v, 2));
                m[mi][h] = v;
            }
        if ((lane & 3) == 0) {
#pragma unroll
            for (int mi = 0; mi < 4; mi++)
#pragma unroll
                for (int h = 0; h < 2; h++) {
                    int row = wm + mi * 16 + rq + h * 8;
                    bufMax[row * 4 + (wid & 3)] = m[mi][h];
                }
        }
        __syncthreads();

        float Mx[4][2];
#pragma unroll
        for (int mi = 0; mi < 4; mi++)
#pragma unroll
            for (int h = 0; h < 2; h++) {
                int row = wm + mi * 16 + rq + h * 8;
                float a0 = bufMax[row * 4 + 0], a1 = bufMax[row * 4 + 1];
                float a2 = bufMax[row * 4 + 2], a3 = bufMax[row * 4 + 3];
                Mx[mi][h] = fmaxf(fmaxf(a0, a1), fmaxf(a2, a3));
            }

        float s[4][2];
#pragma unroll
        for (int mi = 0; mi < 4; mi++)
#pragma unroll
            for (int h = 0; h < 2; h++) {
                float v = 0.0f;
#pragma unroll
                for (int nj = 0; nj < 4; nj++) {
                    float e0 = __expf(acc[mi][nj][h * 2]     - Mx[mi][h]);
                    float e1 = __expf(acc[mi][nj][h * 2 + 1] - Mx[mi][h]);
                    acc[mi][nj][h * 2]     = e0;
                    acc[mi][nj][h * 2 + 1] = e1;
                    v += e0 + e1;
                }
                v += __shfl_xor_sync(0xffffffffu, v, 1);
                v += __shfl_xor_sync(0xffffffffu, v, 2);
                s[mi][h] = v;
            }
        if ((lane & 3) == 0) {
#pragma unroll
            for (int mi = 0; mi < 4; mi++)
#pragma unroll
                for (int h = 0; h < 2; h++) {
                    int row = wm + mi * 16 + rq + h * 8;
                    bufSum[row * 4 + (wid & 3)] = s[mi][h];
                }
        }
        __syncthreads();

#pragma unroll
        for (int mi = 0; mi < 4; mi++)
#pragma unroll
            for (int h = 0; h < 2; h++) {
                int row = wm + mi * 16 + rq + h * 8;
                float inv = 1.0f / (bufSum[row * 4 + 0] + bufSum[row * 4 + 1]
                                  + bufSum[row * 4 + 2] + bufSum[row * 4 + 3]);
#pragma unroll
                for (int nj = 0; nj < 4; nj++) {
                    int col = wn + nj * 8 + cq;
                    float f0 = acc[mi][nj][h * 2]     * inv;
                    float f1 = acc[mi][nj][h * 2 + 1] * inv;
                    __nv_bfloat16 h0 = __float2bfloat16(f0);
                    __nv_bfloat16 h1 = __float2bfloat16(f1);
                    __nv_bfloat16 l0 = __float2bfloat16(f0 - __bfloat162float(h0));
                    __nv_bfloat16 l1 = __float2bfloat16(f1 - __bfloat162float(h1));
                    uint32_t off = (uint32_t)(row * S_PITCH + col) * 2;
                    *(uint32_t*)(dyn + SH_OFF + off) = pack_bf2(h0, h1);
                    *(uint32_t*)(dyn + SL_OFF + off) = pack_bf2(l0, l1);
                }
            }
    }
    __syncthreads();

    // ================= Phase 2: Z = S @ V, two 128-col halves =================
    const uint32_t aoff2 = (uint32_t)((wm + (lane & 15)) * (S_PITCH * 2)
                                      + (lane >> 4) * 16);
    const uint32_t bro = (uint32_t)((lane & 15) * V2_PITCHB + (lane >> 4) * 16);
    const int wn2 = (wid & 3) * 32;

#pragma unroll
    for (int h = 0; h < 2; h++) {
        float acc2[4][4][4];
#pragma unroll
        for (int i = 0; i < 4; i++)
#pragma unroll
            for (int j = 0; j < 4; j++)
#pragma unroll
                for (int r = 0; r < 4; r++) acc2[i][j][r] = 0.0f;

        v_load2(sb + V_OFF + 0 * V2_STAGE, vh, vl, 0, h, tid);
        CP_COMMIT();
        v_load2(sb + V_OFF + 1 * V2_STAGE, vh, vl, 16, h, tid);
        CP_COMMIT();

        for (int c = 0; c < 8; c++) {
            const uint32_t st = sb + V_OFF + (c & 1) * V2_STAGE;
            CP_WAIT1();
            __syncthreads();

            const uint32_t acol = (uint32_t)(c * 32);

            uint32_t ah[4][4], bh[2][4];
#pragma unroll
            for (int mi = 0; mi < 4; mi++)
                ldsm4(ah[mi], sb + SH_OFF + aoff2 + mi * (16 * S_PITCH * 2) + acol);
#pragma unroll
            for (int nb = 0; nb < 2; nb++)
                ldsm4t(bh[nb], st + bro + (uint32_t)((wn2 + nb * 16) * 2));
#pragma unroll
            for (int mi = 0; mi < 4; mi++)
#pragma unroll
                for (int nj = 0; nj < 4; nj++)
                    mma16816(acc2[mi][nj], ah[mi], bh[nj >> 1][(nj & 1) * 2],
                             bh[nj >> 1][(nj & 1) * 2 + 1]);

            uint32_t bl[2][4];
#pragma unroll
            for (int nb = 0; nb < 2; nb++)
                ldsm4t(bl[nb], st + V2_TILE + bro + (uint32_t)((wn2 + nb * 16) * 2));
#pragma unroll
            for (int mi = 0; mi < 4; mi++)
#pragma unroll
                for (int nj = 0; nj < 4; nj++)
                    mma16816(acc2[mi][nj], ah[mi], bl[nj >> 1][(nj & 1) * 2],
                             bl[nj >> 1][(nj & 1) * 2 + 1]);

            uint32_t al[4][4];
#pragma unroll
            for (int mi = 0; mi < 4; mi++)
                ldsm4(al[mi], sb + SL_OFF + aoff2 + mi * (16 * S_PITCH * 2) + acol);
#pragma unroll
            for (int mi = 0; mi < 4; mi++)
#pragma unroll
                for (int nj = 0; nj < 4; nj++)
                    mma16816(acc2[mi][nj], al[mi], bh[nj >> 1][(nj & 1) * 2],
                             bh[nj >> 1][(nj & 1) * 2 + 1]);

            __syncthreads();
            if (c + 2 < 8)
                v_load2(st, vh, vl, (c + 2) * 16, h, tid);
            CP_COMMIT();
        }

#pragma unroll
        for (int nj = 0; nj < 4; nj++) {
            const int col = h * 128 + wn2 + nj * 8 + cq;
#pragma unroll
            for (int mi = 0; mi < 4; mi++) {
                const int row = wm + mi * 16 + rq;
                *(float2*)(ob + (size_t)row * N_V + col) =
                    make_float2(acc2[mi][nj][0], acc2[mi][nj][1]);
                *(float2*)(ob + (size_t)(row + 8) * N_V + col) =
                    make_float2(acc2[mi][nj][2], acc2[mi][nj][3]);
            }
        }
        __syncthreads();
    }
}

// ---------------------------------------------------------------------------
extern "C" void kernel_launch(void* const* d_in, const int* in_sizes, int n_in,
                              void* d_out, int out_size)
{
    const float* x  = (const float*)d_in[0];
    const float* Wq = (const float*)d_in[1];
    const float* bq = (const float*)d_in[2];
    const float* Wk = (const float*)d_in[3];
    const float* bk = (const float*)d_in[4];
    const float* Wv = (const float*)d_in[5];
    const float* bv = (const float*)d_in[6];
    float* out = (float*)d_out;

    conv_x<<<4096, 256>>>(x);
    conv_w<<<dim3(64, 3), 256>>>(Wq, Wk, Wv);

    cudaFuncSetAttribute(gemm_mma, cudaFuncAttributeMaxDynamicSharedMemorySize,
                         GEMM_SMEM);
    gemm_mma<<<dim3(6, 1024), 256, GEMM_SMEM>>>(bq, bk, bv);

    cudaFuncSetAttribute(attn_tc, cudaFuncAttributeMaxDynamicSharedMemorySize,
                         ATTN_SMEM);
    attn_tc<<<BD, 256, ATTN_SMEM>>>(out);
}

// round 14
// speedup vs baseline: 1.0307x; 1.0307x over previous
#include <cuda_runtime.h>
#include <cuda_bf16.h>
#include <cstdint>

// Problem constants
#define T_DIM 1024
#define N_QK  256
#define N_V   256
#define C_DIM 128
#define BD    1024
#define M_TOT (BD * C_DIM)   // 131072

// ---------------------------------------------------------------------------
// Scratch (__device__ globals; alloc-free rule)
// ---------------------------------------------------------------------------
__device__ __align__(16) __nv_bfloat16 g_qh[(size_t)M_TOT * N_QK];
__device__ __align__(16) __nv_bfloat16 g_ql[(size_t)M_TOT * N_QK];
__device__ __align__(16) __nv_bfloat16 g_kh[(size_t)M_TOT * N_QK];
__device__ __align__(16) __nv_bfloat16 g_kl[(size_t)M_TOT * N_QK];
__device__ __align__(16) __nv_bfloat16 g_vh[(size_t)M_TOT * N_V];
__device__ __align__(16) __nv_bfloat16 g_vl[(size_t)M_TOT * N_V];

__device__ __align__(16) __nv_bfloat16 g_xh[(size_t)M_TOT * T_DIM];
__device__ __align__(16) __nv_bfloat16 g_xl[(size_t)M_TOT * T_DIM];
__device__ __align__(16) __nv_bfloat16 g_wh[3 * 256 * T_DIM];
__device__ __align__(16) __nv_bfloat16 g_wl[3 * 256 * T_DIM];

// ---------------------------------------------------------------------------
// Helpers
// ---------------------------------------------------------------------------
__device__ __forceinline__ uint32_t smem_u32(const void* p) {
    uint32_t a;
    asm("{ .reg .u64 t; cvta.to.shared.u64 t, %1; cvt.u32.u64 %0, t; }"
        : "=r"(a) : "l"(p));
    return a;
}
__device__ __forceinline__ void cp16(uint32_t dst, const void* src) {
    asm volatile("cp.async.cg.shared.global [%0], [%1], 16;"
                 :: "r"(dst), "l"(src) : "memory");
}
#define CP_COMMIT() asm volatile("cp.async.commit_group;" ::: "memory")
#define CP_WAIT1()  asm volatile("cp.async.wait_group 1;" ::: "memory")

__device__ __forceinline__ void ldsm4(uint32_t* r, uint32_t addr) {
    asm volatile("ldmatrix.sync.aligned.m8n8.x4.shared.b16 {%0,%1,%2,%3}, [%4];"
                 : "=r"(r[0]), "=r"(r[1]), "=r"(r[2]), "=r"(r[3]) : "r"(addr));
}
__device__ __forceinline__ void ldsm4t(uint32_t* r, uint32_t addr) {
    asm volatile("ldmatrix.sync.aligned.m8n8.x4.trans.shared.b16 {%0,%1,%2,%3}, [%4];"
                 : "=r"(r[0]), "=r"(r[1]), "=r"(r[2]), "=r"(r[3]) : "r"(addr));
}
__device__ __forceinline__ void mma16816(float* d, const uint32_t* a,
                                         uint32_t b0, uint32_t b1) {
    asm volatile(
        "mma.sync.aligned.m16n8k16.row.col.f32.bf16.bf16.f32 "
        "{%0,%1,%2,%3}, {%4,%5,%6,%7}, {%8,%9}, {%0,%1,%2,%3};"
        : "+f"(d[0]), "+f"(d[1]), "+f"(d[2]), "+f"(d[3])
        : "r"(a[0]), "r"(a[1]), "r"(a[2]), "r"(a[3]), "r"(b0), "r"(b1));
}
__device__ __forceinline__ uint32_t pack_bf2(__nv_bfloat16 a, __nv_bfloat16 b) {
    return (uint32_t)__bfloat16_as_ushort(a) | ((uint32_t)__bfloat16_as_ushort(b) << 16);
}

// ---------------------------------------------------------------------------
// Convert kernels: fp32 -> bf16 hi/lo split
// ---------------------------------------------------------------------------
__global__ void __launch_bounds__(256) conv_x(const float* __restrict__ x)
{
    const size_t n4 = (size_t)M_TOT * T_DIM / 4;
    const size_t stride = (size_t)gridDim.x * blockDim.x;
    uint2* __restrict__ xh = (uint2*)g_xh;
    uint2* __restrict__ xl = (uint2*)g_xl;
    for (size_t i = (size_t)blockIdx.x * blockDim.x + threadIdx.x; i < n4; i += stride) {
        float4 f = ((const float4*)x)[i];
        __nv_bfloat16 h0 = __float2bfloat16(f.x);
        __nv_bfloat16 h1 = __float2bfloat16(f.y);
        __nv_bfloat16 h2 = __float2bfloat16(f.z);
        __nv_bfloat16 h3 = __float2bfloat16(f.w);
        __nv_bfloat16 l0 = __float2bfloat16(f.x - __bfloat162float(h0));
        __nv_bfloat16 l1 = __float2bfloat16(f.y - __bfloat162float(h1));
        __nv_bfloat16 l2 = __float2bfloat16(f.z - __bfloat162float(h2));
        __nv_bfloat16 l3 = __float2bfloat16(f.w - __bfloat162float(h3));
        xh[i] = make_uint2(pack_bf2(h0, h1), pack_bf2(h2, h3));
        xl[i] = make_uint2(pack_bf2(l0, l1), pack_bf2(l2, l3));
    }
}

__global__ void __launch_bounds__(256) conv_w(const float* __restrict__ Wq,
                                              const float* __restrict__ Wk,
                                              const float* __restrict__ Wv)
{
    const int mat = blockIdx.y;
    const float* W = (mat == 0) ? Wq : (mat == 1) ? Wk : Wv;
    const size_t n4 = 256 * T_DIM / 4;
    const size_t base = (size_t)mat * n4;
    uint2* __restrict__ wh = (uint2*)g_wh;
    uint2* __restrict__ wl = (uint2*)g_wl;
    for (size_t i = (size_t)blockIdx.x * blockDim.x + threadIdx.x; i < n4;
         i += (size_t)gridDim.x * blockDim.x) {
        float4 f = ((const float4*)W)[i];
        __nv_bfloat16 h0 = __float2bfloat16(f.x);
        __nv_bfloat16 h1 = __float2bfloat16(f.y);
        __nv_bfloat16 h2 = __float2bfloat16(f.z);
        __nv_bfloat16 h3 = __float2bfloat16(f.w);
        __nv_bfloat16 l0 = __float2bfloat16(f.x - __bfloat162float(h0));
        __nv_bfloat16 l1 = __float2bfloat16(f.y - __bfloat162float(h1));
        __nv_bfloat16 l2 = __float2bfloat16(f.z - __bfloat162float(h2));
        __nv_bfloat16 l3 = __float2bfloat16(f.w - __bfloat162float(h3));
        wh[base + i] = make_uint2(pack_bf2(h0, h1), pack_bf2(h2, h3));
        wl[base + i] = make_uint2(pack_bf2(l0, l1), pack_bf2(l2, l3));
    }
}

// ---------------------------------------------------------------------------
// HMMA GEMM (R7 config + al-ldsm hoist): 128x128 CTA tile, 256 thr (8 warps,
// 2x4), 64x32 warp tile, BK=32, 2 stages, 2 CTAs/SM.
// ---------------------------------------------------------------------------
#define ROW_B   80
#define TILE_B  (128 * ROW_B)
#define OFF_AH  0
#define OFF_AL  (1 * TILE_B)
#define OFF_BH  (2 * TILE_B)
#define OFF_BL  (3 * TILE_B)
#define STAGE_B (4 * TILE_B)
#define GEMM_SMEM (2 * STAGE_B)
#define NCHUNK  32

__device__ __forceinline__ void load_chunk(
    uint32_t st, const __nv_bfloat16* __restrict__ xh,
    const __nv_bfloat16* __restrict__ xl,
    const __nv_bfloat16* __restrict__ wh,
    const __nv_bfloat16* __restrict__ wl, int k0, int tid)
{
#pragma unroll
    for (int t = 0; t < 2; t++) {
        int op = tid + t * 256;
        int r  = op >> 2;
        int ch = op & 3;
        uint32_t doff = (uint32_t)(r * ROW_B + ch * 16);
        size_t soff = (size_t)r * T_DIM + k0 + ch * 8;
        cp16(st + OFF_AH + doff, xh + soff);
        cp16(st + OFF_AL + doff, xl + soff);
        cp16(st + OFF_BH + doff, wh + soff);
        cp16(st + OFF_BL + doff, wl + soff);
    }
}

__global__ void __launch_bounds__(256, 2) gemm_mma(
    const float* __restrict__ bq, const float* __restrict__ bk,
    const float* __restrict__ bv)
{
    extern __shared__ __align__(16) char dyn[];

    const int tid  = threadIdx.x;
    const int lane = tid & 31;
    const int wid  = tid >> 5;
    const int mat  = blockIdx.x >> 1;
    const int bn   = blockIdx.x & 1;
    const int bm   = blockIdx.y;

    const int wm = (wid >> 2) * 64;
    const int wn = (wid & 3) * 32;

    const __nv_bfloat16* xh = g_xh + (size_t)bm * 128 * T_DIM;
    const __nv_bfloat16* xl = g_xl + (size_t)bm * 128 * T_DIM;
    const __nv_bfloat16* wh = g_wh + ((size_t)mat * 256 + bn * 128) * T_DIM;
    const __nv_bfloat16* wl = g_wl + ((size_t)mat * 256 + bn * 128) * T_DIM;
    const float* bias = (mat == 0) ? bq : (mat == 1) ? bk : bv;
    __nv_bfloat16* outh = ((mat == 0) ? g_qh : (mat == 1) ? g_kh : g_vh)
                          + (size_t)bm * 128 * 256 + bn * 128;
    __nv_bfloat16* outl = ((mat == 0) ? g_ql : (mat == 1) ? g_kl : g_vl)
                          + (size_t)bm * 128 * 256 + bn * 128;

    const uint32_t sbase = smem_u32(dyn);

    float acc[4][4][4];
#pragma unroll
    for (int i = 0; i < 4; i++)
#pragma unroll
        for (int j = 0; j < 4; j++)
#pragma unroll
            for (int r = 0; r < 4; r++) acc[i][j][r] = 0.0f;

    const uint32_t aoff = (uint32_t)((wm + (lane & 15)) * ROW_B + (lane >> 4) * 16);
    const uint32_t boff = (uint32_t)((wn + ((lane >> 4) << 3) + (lane & 7)) * ROW_B
                                     + ((lane >> 3) & 1) * 16);

    load_chunk(sbase + 0 * STAGE_B, xh, xl, wh, wl, 0, tid);
    CP_COMMIT();
    load_chunk(sbase + 1 * STAGE_B, xh, xl, wh, wl, 32, tid);
    CP_COMMIT();

    for (int c = 0; c < NCHUNK; c++) {
        const uint32_t st = sbase + (c & 1) * STAGE_B;
        CP_WAIT1();
        __syncthreads();

#pragma unroll
        for (int ks = 0; ks < 2; ks++) {
            const uint32_t kadd = (uint32_t)(ks * 32);
            // hoist ah, al, bh ldsm before any MMA (al overlaps pass-1 MMAs)
            uint32_t ah[4][4], al[4][4], bh[2][4];
#pragma unroll
            for (int mi = 0; mi < 4; mi++)
                ldsm4(ah[mi], st + OFF_AH + aoff + mi * (16 * ROW_B) + kadd);
#pragma unroll
            for (int mi = 0; mi < 4; mi++)
                ldsm4(al[mi], st + OFF_AL + aoff + mi * (16 * ROW_B) + kadd);
#pragma unroll
            for (int np = 0; np < 2; np++)
                ldsm4(bh[np], st + OFF_BH + boff + np * (16 * ROW_B) + kadd);

            // pass 1: Xh @ Wh
#pragma unroll
            for (int mi = 0; mi < 4; mi++)
#pragma unroll
                for (int nj = 0; nj < 4; nj++)
                    mma16816(acc[mi][nj], ah[mi], bh[nj >> 1][(nj & 1) * 2],
                             bh[nj >> 1][(nj & 1) * 2 + 1]);

            // pass 3 (moved up): Xl @ Wh — operands already resident
#pragma unroll
            for (int mi = 0; mi < 4; mi++)
#pragma unroll
                for (int nj = 0; nj < 4; nj++)
                    mma16816(acc[mi][nj], al[mi], bh[nj >> 1][(nj & 1) * 2],
                             bh[nj >> 1][(nj & 1) * 2 + 1]);

            // pass 2: Xh @ Wl
            uint32_t bl[2][4];
#pragma unroll
            for (int np = 0; np < 2; np++)
                ldsm4(bl[np], st + OFF_BL + boff + np * (16 * ROW_B) + kadd);
#pragma unroll
            for (int mi = 0; mi < 4; mi++)
#pragma unroll
                for (int nj = 0; nj < 4; nj++)
                    mma16816(acc[mi][nj], ah[mi], bl[nj >> 1][(nj & 1) * 2],
                             bl[nj >> 1][(nj & 1) * 2 + 1]);
        }

        __syncthreads();
        if (c + 2 < NCHUNK)
            load_chunk(st, xh, xl, wh, wl, (c + 2) * 32, tid);
        CP_COMMIT();
    }

    const int rq = lane >> 2;
    const int cq = (lane & 3) * 2;
#pragma unroll
    for (int nj = 0; nj < 4; nj++) {
        const int col = wn + nj * 8 + cq;
        const float b0 = bias[bn * 128 + col];
        const float b1 = bias[bn * 128 + col + 1];
#pragma unroll
        for (int mi = 0; mi < 4; mi++) {
            const int row = wm + mi * 16 + rq;
#pragma unroll
            for (int half = 0; half < 2; half++) {
                const float v0 = acc[mi][nj][half * 2 + 0] + b0;
                const float v1 = acc[mi][nj][half * 2 + 1] + b1;
                __nv_bfloat16 h0 = __float2bfloat16(v0);
                __nv_bfloat16 h1 = __float2bfloat16(v1);
                __nv_bfloat16 l0 = __float2bfloat16(v0 - __bfloat162float(h0));
                __nv_bfloat16 l1 = __float2bfloat16(v1 - __bfloat162float(h1));
                const size_t off = (size_t)(row + half * 8) * 256 + col;
                *(uint32_t*)(outh + off) = pack_bf2(h0, h1);
                *(uint32_t*)(outl + off) = pack_bf2(l0, l1);
            }
        }
    }
}

// ---------------------------------------------------------------------------
// Tensor-core attention (R10-exact): 2 CTAs/SM, register softmax,
// phase-2 in two 128-col halves.
// ---------------------------------------------------------------------------
#define P1_ROWB  80
#define P1_TILE  (128 * P1_ROWB)
#define P1_QH    0
#define P1_QL    (1 * P1_TILE)
#define P1_KH    (2 * P1_TILE)
#define P1_KL    (3 * P1_TILE)
#define P1_STAGE (4 * P1_TILE)          // 40960
#define R1_SIZE  (2 * P1_STAGE)         // 81920

#define S_PITCH  136
#define SH_OFF   0
#define SL_OFF   (128 * S_PITCH * 2)    // 34816

#define RB_OFF   R1_SIZE
#define BUFMAX_OFF RB_OFF
#define BUFSUM_OFF (RB_OFF + 2048)
#define V_OFF    (RB_OFF + 4096)
#define V2_PITCHB 272
#define V2_TILE  (16 * V2_PITCHB)       // 4352
#define V2_STAGE (2 * V2_TILE)          // 8704
#define ATTN_SMEM (V_OFF + 2 * V2_STAGE)   // 103424

__device__ __forceinline__ void p1_load(
    uint32_t st, const __nv_bfloat16* __restrict__ qh,
    const __nv_bfloat16* __restrict__ ql,
    const __nv_bfloat16* __restrict__ kh,
    const __nv_bfloat16* __restrict__ kl, int k0, int tid)
{
#pragma unroll
    for (int t = 0; t < 2; t++) {
        int op = tid + t * 256;
        int r  = op >> 2;
        int ch = op & 3;
        uint32_t doff = (uint32_t)(r * P1_ROWB + ch * 16);
        size_t soff = (size_t)r * N_QK + k0 + ch * 8;
        cp16(st + P1_QH + doff, qh + soff);
        cp16(st + P1_QL + doff, ql + soff);
        cp16(st + P1_KH + doff, kh + soff);
        cp16(st + P1_KL + doff, kl + soff);
    }
}

__device__ __forceinline__ void v_load2(
    uint32_t st, const __nv_bfloat16* __restrict__ vh,
    const __nv_bfloat16* __restrict__ vl, int k0, int h, int tid)
{
    int r  = tid >> 4;
    int ch = tid & 15;
    uint32_t doff = (uint32_t)(r * V2_PITCHB + ch * 16);
    size_t soff = (size_t)(k0 + r) * N_V + h * 128 + ch * 8;
    cp16(st + doff, vh + soff);
    cp16(st + V2_TILE + doff, vl + soff);
}

__global__ void __launch_bounds__(256, 2) attn_tc(float* __restrict__ out)
{
    extern __shared__ __align__(16) char dyn[];
    const uint32_t sb = smem_u32(dyn);

    const int tid  = threadIdx.x;
    const int lane = tid & 31;
    const int wid  = tid >> 5;
    const int bd   = blockIdx.x;

    const __nv_bfloat16* qh = g_qh + (size_t)bd * C_DIM * N_QK;
    const __nv_bfloat16* ql = g_ql + (size_t)bd * C_DIM * N_QK;
    const __nv_bfloat16* kh = g_kh + (size_t)bd * C_DIM * N_QK;
    const __nv_bfloat16* kl = g_kl + (size_t)bd * C_DIM * N_QK;
    const __nv_bfloat16* vh = g_vh + (size_t)bd * C_DIM * N_V;
    const __nv_bfloat16* vl = g_vl + (size_t)bd * C_DIM * N_V;
    float* ob = out + (size_t)bd * C_DIM * N_V;

    const int wm = (wid >> 2) * 64;
    const int wn = (wid & 3) * 32;
    const int rq = lane >> 2;
    const int cq = (lane & 3) * 2;

    float* bufMax = (float*)(dyn + BUFMAX_OFF);
    float* bufSum = (float*)(dyn + BUFSUM_OFF);

    // ================= Phase 1: S = q @ k^T (regs) =================
    float acc[4][4][4];
#pragma unroll
    for (int i = 0; i < 4; i++)
#pragma unroll
        for (int j = 0; j < 4; j++)
#pragma unroll
            for (int r = 0; r < 4; r++) acc[i][j][r] = 0.0f;

    {
        const uint32_t aoff = (uint32_t)((wm + (lane & 15)) * P1_ROWB + (lane >> 4) * 16);
        const uint32_t boff = (uint32_t)((wn + ((lane >> 4) << 3) + (lane & 7)) * P1_ROWB
                                         + ((lane >> 3) & 1) * 16);

        p1_load(sb + 0 * P1_STAGE, qh, ql, kh, kl, 0, tid);
        CP_COMMIT();
        p1_load(sb + 1 * P1_STAGE, qh, ql, kh, kl, 32, tid);
        CP_COMMIT();

        for (int c = 0; c < 8; c++) {
            const uint32_t st = sb + (c & 1) * P1_STAGE;
            CP_WAIT1();
            __syncthreads();

#pragma unroll
            for (int ks = 0; ks < 2; ks++) {
                const uint32_t kadd = (uint32_t)(ks * 32);
                uint32_t ah[4][4], bh[2][4];
#pragma unroll
                for (int mi = 0; mi < 4; mi++)
                    ldsm4(ah[mi], st + P1_QH + aoff + mi * (16 * P1_ROWB) + kadd);
#pragma unroll
                for (int np = 0; np < 2; np++)
                    ldsm4(bh[np], st + P1_KH + boff + np * (16 * P1_ROWB) + kadd);
#pragma unroll
                for (int mi = 0; mi < 4; mi++)
#pragma unroll
                    for (int nj = 0; nj < 4; nj++)
                        mma16816(acc[mi][nj], ah[mi], bh[nj >> 1][(nj & 1) * 2],
                                 bh[nj >> 1][(nj & 1) * 2 + 1]);

                uint32_t bl[2][4];
#pragma unroll
                for (int np = 0; np < 2; np++)
                    ldsm4(bl[np], st + P1_KL + boff + np * (16 * P1_ROWB) + kadd);
#pragma unroll
                for (int mi = 0; mi < 4; mi++)
#pragma unroll
                    for (int nj = 0; nj < 4; nj++)
                        mma16816(acc[mi][nj], ah[mi], bl[nj >> 1][(nj & 1) * 2],
                                 bl[nj >> 1][(nj & 1) * 2 + 1]);

                uint32_t al[4][4];
#pragma unroll
                for (int mi = 0; mi < 4; mi++)
                    ldsm4(al[mi], st + P1_QL + aoff + mi * (16 * P1_ROWB) + kadd);
#pragma unroll
                for (int mi = 0; mi < 4; mi++)
#pragma unroll
                    for (int nj = 0; nj < 4; nj++)
                        mma16816(acc[mi][nj], al[mi], bh[nj >> 1][(nj & 1) * 2],
                                 bh[nj >> 1][(nj & 1) * 2 + 1]);
            }

            __syncthreads();
            if (c + 2 < 8)
                p1_load(st, qh, ql, kh, kl, (c + 2) * 32, tid);
            CP_COMMIT();
        }
    }

    // ================= Softmax from registers =================
    {
        const float scale = 0.0625f;
#pragma unroll
        for (int mi = 0; mi < 4; mi++)
#pragma unroll
            for (int nj = 0; nj < 4; nj++)
#pragma unroll
                for (int r = 0; r < 4; r++) acc[mi][nj][r] *= scale;

        float m[4][2];
#pragma unroll
        for (int mi = 0; mi < 4; mi++)
#pragma unroll
            for (int h = 0; h < 2; h++) {
                float v = -1e30f;
#pragma unroll
                for (int nj = 0; nj < 4; nj++) {
                    v = fmaxf(v, acc[mi][nj][h * 2]);
                    v = fmaxf(v, acc[mi][nj][h * 2 + 1]);
                }
                v = fmaxf(v, __shfl_xor_sync(0xffffffffu, v, 1));
                v = fmaxf(v, __shfl_xor_sync(0xffffffffu, v, 2));
                m[mi][h] = v;
            }
        if ((lane & 3) == 0) {
#pragma unroll
            for (int mi = 0; mi < 4; mi++)
#pragma unroll
                for (int h = 0; h < 2; h++) {
                    int row = wm + mi * 16 + rq + h * 8;
                    bufMax[row * 4 + (wid & 3)] = m[mi][h];
                }
        }
        __syncthreads();

        float Mx[4][2];
#pragma unroll
        for (int mi = 0; mi < 4; mi++)
#pragma unroll
            for (int h = 0; h < 2; h++) {
                int row = wm + mi * 16 + rq + h * 8;
                float a0 = bufMax[row * 4 + 0], a1 = bufMax[row * 4 + 1];
                float a2 = bufMax[row * 4 + 2], a3 = bufMax[row * 4 + 3];
                Mx[mi][h] = fmaxf(fmaxf(a0, a1), fmaxf(a2, a3));
            }

        float s[4][2];
#pragma unroll
        for (int mi = 0; mi < 4; mi++)
#pragma unroll
            for (int h = 0; h < 2; h++) {
                float v = 0.0f;
#pragma unroll
                for (int nj = 0; nj < 4; nj++) {
                    float e0 = __expf(acc[mi][nj][h * 2]     - Mx[mi][h]);
                    float e1 = __expf(acc[mi][nj][h * 2 + 1] - Mx[mi][h]);
                    acc[mi][nj][h * 2]     = e0;
                    acc[mi][nj][h * 2 + 1] = e1;
                    v += e0 + e1;
                }
                v += __shfl_xor_sync(0xffffffffu, v, 1);
                v += __shfl_xor_sync(0xffffffffu, v, 2);
                s[mi][h] = v;
            }
        if ((lane & 3) == 0) {
#pragma unroll
            for (int mi = 0; mi < 4; mi++)
#pragma unroll
                for (int h = 0; h < 2; h++) {
                    int row = wm + mi * 16 + rq + h * 8;
                    bufSum[row * 4 + (wid & 3)] = s[mi][h];
                }
        }
        __syncthreads();

#pragma unroll
        for (int mi = 0; mi < 4; mi++)
#pragma unroll
            for (int h = 0; h < 2; h++) {
                int row = wm + mi * 16 + rq + h * 8;
                float inv = 1.0f / (bufSum[row * 4 + 0] + bufSum[row * 4 + 1]
                                  + bufSum[row * 4 + 2] + bufSum[row * 4 + 3]);
#pragma unroll
                for (int nj = 0; nj < 4; nj++) {
                    int col = wn + nj * 8 + cq;
                    float f0 = acc[mi][nj][h * 2]     * inv;
                    float f1 = acc[mi][nj][h * 2 + 1] * inv;
                    __nv_bfloat16 h0 = __float2bfloat16(f0);
                    __nv_bfloat16 h1 = __float2bfloat16(f1);
                    __nv_bfloat16 l0 = __float2bfloat16(f0 - __bfloat162float(h0));
                    __nv_bfloat16 l1 = __float2bfloat16(f1 - __bfloat162float(h1));
                    uint32_t off = (uint32_t)(row * S_PITCH + col) * 2;
                    *(uint32_t*)(dyn + SH_OFF + off) = pack_bf2(h0, h1);
                    *(uint32_t*)(dyn + SL_OFF + off) = pack_bf2(l0, l1);
                }
            }
    }
    __syncthreads();

    // ================= Phase 2: Z = S @ V, two 128-col halves =================
    const uint32_t aoff2 = (uint32_t)((wm + (lane & 15)) * (S_PITCH * 2)
                                      + (lane >> 4) * 16);
    const uint32_t bro = (uint32_t)((lane & 15) * V2_PITCHB + (lane >> 4) * 16);
    const int wn2 = (wid & 3) * 32;

#pragma unroll
    for (int h = 0; h < 2; h++) {
        float acc2[4][4][4];
#pragma unroll
        for (int i = 0; i < 4; i++)
#pragma unroll
            for (int j = 0; j < 4; j++)
#pragma unroll
                for (int r = 0; r < 4; r++) acc2[i][j][r] = 0.0f;

        v_load2(sb + V_OFF + 0 * V2_STAGE, vh, vl, 0, h, tid);
        CP_COMMIT();
        v_load2(sb + V_OFF + 1 * V2_STAGE, vh, vl, 16, h, tid);
        CP_COMMIT();

        for (int c = 0; c < 8; c++) {
            const uint32_t st = sb + V_OFF + (c & 1) * V2_STAGE;
            CP_WAIT1();
            __syncthreads();

            const uint32_t acol = (uint32_t)(c * 32);

            uint32_t ah[4][4], bh[2][4];
#pragma unroll
            for (int mi = 0; mi < 4; mi++)
                ldsm4(ah[mi], sb + SH_OFF + aoff2 + mi * (16 * S_PITCH * 2) + acol);
#pragma unroll
            for (int nb = 0; nb < 2; nb++)
                ldsm4t(bh[nb], st + bro + (uint32_t)((wn2 + nb * 16) * 2));
#pragma unroll
            for (int mi = 0; mi < 4; mi++)
#pragma unroll
                for (int nj = 0; nj < 4; nj++)
                    mma16816(acc2[mi][nj], ah[mi], bh[nj >> 1][(nj & 1) * 2],
                             bh[nj >> 1][(nj & 1) * 2 + 1]);

            uint32_t bl[2][4];
#pragma unroll
            for (int nb = 0; nb < 2; nb++)
                ldsm4t(bl[nb], st + V2_TILE + bro + (uint32_t)((wn2 + nb * 16) * 2));
#pragma unroll
            for (int mi = 0; mi < 4; mi++)
#pragma unroll
                for (int nj = 0; nj < 4; nj++)
                    mma16816(acc2[mi][nj], ah[mi], bl[nj >> 1][(nj & 1) * 2],
                             bl[nj >> 1][(nj & 1) * 2 + 1]);

            uint32_t al[4][4];
#pragma unroll
            for (int mi = 0; mi < 4; mi++)
                ldsm4(al[mi], sb + SL_OFF + aoff2 + mi * (16 * S_PITCH * 2) + acol);
#pragma unroll
            for (int mi = 0; mi < 4; mi++)
#pragma unroll
                for (int nj = 0; nj < 4; nj++)
                    mma16816(acc2[mi][nj], al[mi], bh[nj >> 1][(nj & 1) * 2],
                             bh[nj >> 1][(nj & 1) * 2 + 1]);

            __syncthreads();
            if (c + 2 < 8)
                v_load2(st, vh, vl, (c + 2) * 16, h, tid);
            CP_COMMIT();
        }

#pragma unroll
        for (int nj = 0; nj < 4; nj++) {
            const int col = h * 128 + wn2 + nj * 8 + cq;
#pragma unroll
            for (int mi = 0; mi < 4; mi++) {
                const int row = wm + mi * 16 + rq;
                *(float2*)(ob + (size_t)row * N_V + col) =
                    make_float2(acc2[mi][nj][0], acc2[mi][nj][1]);
                *(float2*)(ob + (size_t)(row + 8) * N_V + col) =
                    make_float2(acc2[mi][nj][2], acc2[mi][nj][3]);
            }
        }
        __syncthreads();
    }
}

// ---------------------------------------------------------------------------
extern "C" void kernel_launch(void* const* d_in, const int* in_sizes, int n_in,
                              void* d_out, int out_size)
{
    const float* x  = (const float*)d_in[0];
    const float* Wq = (const float*)d_in[1];
    const float* bq = (const float*)d_in[2];
    const float* Wk = (const float*)d_in[3];
    const float* bk = (const float*)d_in[4];
    const float* Wv = (const float*)d_in[5];
    const float* bv = (const float*)d_in[6];
    float* out = (float*)d_out;

    conv_x<<<4096, 256>>>(x);
    conv_w<<<dim3(64, 3), 256>>>(Wq, Wk, Wv);

    cudaFuncSetAttribute(gemm_mma, cudaFuncAttributeMaxDynamicSharedMemorySize,
                         GEMM_SMEM);
    gemm_mma<<<dim3(6, 1024), 256, GEMM_SMEM>>>(bq, bk, bv);

    cudaFuncSetAttribute(attn_tc, cudaFuncAttributeMaxDynamicSharedMemorySize,
                         ATTN_SMEM);
    attn_tc<<<BD, 256, ATTN_SMEM>>>(out);
}

// round 16
// speedup vs baseline: 1.0796x; 1.0475x over previous
#include <cuda_runtime.h>
#include <cuda_bf16.h>
#include <cstdint>

// Problem constants
#define T_DIM 1024
#define N_QK  256
#define N_V   256
#define C_DIM 128
#define BD    1024
#define M_TOT (BD * C_DIM)   // 131072

// ---------------------------------------------------------------------------
// Scratch (__device__ globals; alloc-free rule)
// ---------------------------------------------------------------------------
__device__ __align__(16) __nv_bfloat16 g_qh[(size_t)M_TOT * N_QK];
__device__ __align__(16) __nv_bfloat16 g_ql[(size_t)M_TOT * N_QK];
__device__ __align__(16) __nv_bfloat16 g_kh[(size_t)M_TOT * N_QK];
__device__ __align__(16) __nv_bfloat16 g_kl[(size_t)M_TOT * N_QK];
__device__ __align__(16) __nv_bfloat16 g_vh[(size_t)M_TOT * N_V];
__device__ __align__(16) __nv_bfloat16 g_vl[(size_t)M_TOT * N_V];

__device__ __align__(16) __nv_bfloat16 g_xh[(size_t)M_TOT * T_DIM];
__device__ __align__(16) __nv_bfloat16 g_xl[(size_t)M_TOT * T_DIM];
__device__ __align__(16) __nv_bfloat16 g_wh[3 * 256 * T_DIM];
__device__ __align__(16) __nv_bfloat16 g_wl[3 * 256 * T_DIM];

// ---------------------------------------------------------------------------
// Helpers
// ---------------------------------------------------------------------------
__device__ __forceinline__ uint32_t smem_u32(const void* p) {
    uint32_t a;
    asm("{ .reg .u64 t; cvta.to.shared.u64 t, %1; cvt.u32.u64 %0, t; }"
        : "=r"(a) : "l"(p));
    return a;
}
__device__ __forceinline__ void cp16(uint32_t dst, const void* src) {
    asm volatile("cp.async.cg.shared.global [%0], [%1], 16;"
                 :: "r"(dst), "l"(src) : "memory");
}
#define CP_COMMIT() asm volatile("cp.async.commit_group;" ::: "memory")
#define CP_WAIT1()  asm volatile("cp.async.wait_group 1;" ::: "memory")

__device__ __forceinline__ void ldsm4(uint32_t* r, uint32_t addr) {
    asm volatile("ldmatrix.sync.aligned.m8n8.x4.shared.b16 {%0,%1,%2,%3}, [%4];"
                 : "=r"(r[0]), "=r"(r[1]), "=r"(r[2]), "=r"(r[3]) : "r"(addr));
}
__device__ __forceinline__ void ldsm4t(uint32_t* r, uint32_t addr) {
    asm volatile("ldmatrix.sync.aligned.m8n8.x4.trans.shared.b16 {%0,%1,%2,%3}, [%4];"
                 : "=r"(r[0]), "=r"(r[1]), "=r"(r[2]), "=r"(r[3]) : "r"(addr));
}
__device__ __forceinline__ void mma16816(float* d, const uint32_t* a,
                                         uint32_t b0, uint32_t b1) {
    asm volatile(
        "mma.sync.aligned.m16n8k16.row.col.f32.bf16.bf16.f32 "
        "{%0,%1,%2,%3}, {%4,%5,%6,%7}, {%8,%9}, {%0,%1,%2,%3};"
        : "+f"(d[0]), "+f"(d[1]), "+f"(d[2]), "+f"(d[3])
        : "r"(a[0]), "r"(a[1]), "r"(a[2]), "r"(a[3]), "r"(b0), "r"(b1));
}
__device__ __forceinline__ uint32_t pack_bf2(__nv_bfloat16 a, __nv_bfloat16 b) {
    return (uint32_t)__bfloat16_as_ushort(a) | ((uint32_t)__bfloat16_as_ushort(b) << 16);
}

// ---------------------------------------------------------------------------
// Convert kernels: fp32 -> bf16 hi/lo split
// ---------------------------------------------------------------------------
__global__ void __launch_bounds__(256) conv_x(const float* __restrict__ x)
{
    const size_t n4 = (size_t)M_TOT * T_DIM / 4;
    const size_t stride = (size_t)gridDim.x * blockDim.x;
    uint2* __restrict__ xh = (uint2*)g_xh;
    uint2* __restrict__ xl = (uint2*)g_xl;
    for (size_t i = (size_t)blockIdx.x * blockDim.x + threadIdx.x; i < n4; i += stride) {
        float4 f = ((const float4*)x)[i];
        __nv_bfloat16 h0 = __float2bfloat16(f.x);
        __nv_bfloat16 h1 = __float2bfloat16(f.y);
        __nv_bfloat16 h2 = __float2bfloat16(f.z);
        __nv_bfloat16 h3 = __float2bfloat16(f.w);
        __nv_bfloat16 l0 = __float2bfloat16(f.x - __bfloat162float(h0));
        __nv_bfloat16 l1 = __float2bfloat16(f.y - __bfloat162float(h1));
        __nv_bfloat16 l2 = __float2bfloat16(f.z - __bfloat162float(h2));
        __nv_bfloat16 l3 = __float2bfloat16(f.w - __bfloat162float(h3));
        xh[i] = make_uint2(pack_bf2(h0, h1), pack_bf2(h2, h3));
        xl[i] = make_uint2(pack_bf2(l0, l1), pack_bf2(l2, l3));
    }
}

__global__ void __launch_bounds__(256) conv_w(const float* __restrict__ Wq,
                                              const float* __restrict__ Wk,
                                              const float* __restrict__ Wv)
{
    const int mat = blockIdx.y;
    const float* W = (mat == 0) ? Wq : (mat == 1) ? Wk : Wv;
    const size_t n4 = 256 * T_DIM / 4;
    const size_t base = (size_t)mat * n4;
    uint2* __restrict__ wh = (uint2*)g_wh;
    uint2* __restrict__ wl = (uint2*)g_wl;
    for (size_t i = (size_t)blockIdx.x * blockDim.x + threadIdx.x; i < n4;
         i += (size_t)gridDim.x * blockDim.x) {
        float4 f = ((const float4*)W)[i];
        __nv_bfloat16 h0 = __float2bfloat16(f.x);
        __nv_bfloat16 h1 = __float2bfloat16(f.y);
        __nv_bfloat16 h2 = __float2bfloat16(f.z);
        __nv_bfloat16 h3 = __float2bfloat16(f.w);
        __nv_bfloat16 l0 = __float2bfloat16(f.x - __bfloat162float(h0));
        __nv_bfloat16 l1 = __float2bfloat16(f.y - __bfloat162float(h1));
        __nv_bfloat16 l2 = __float2bfloat16(f.z - __bfloat162float(h2));
        __nv_bfloat16 l3 = __float2bfloat16(f.w - __bfloat162float(h3));
        wh[base + i] = make_uint2(pack_bf2(h0, h1), pack_bf2(h2, h3));
        wl[base + i] = make_uint2(pack_bf2(l0, l1), pack_bf2(l2, l3));
    }
}

// ---------------------------------------------------------------------------
// HMMA GEMM (R10-exact): 128x128 CTA tile, 256 thr (8 warps, 2x4), 64x32
// warp tile, BK=32, 2 stages, 2 CTAs/SM.
// ---------------------------------------------------------------------------
#define ROW_B   80
#define TILE_B  (128 * ROW_B)
#define OFF_AH  0
#define OFF_AL  (1 * TILE_B)
#define OFF_BH  (2 * TILE_B)
#define OFF_BL  (3 * TILE_B)
#define STAGE_B (4 * TILE_B)
#define GEMM_SMEM (2 * STAGE_B)
#define NCHUNK  32

__device__ __forceinline__ void load_chunk(
    uint32_t st, const __nv_bfloat16* __restrict__ xh,
    const __nv_bfloat16* __restrict__ xl,
    const __nv_bfloat16* __restrict__ wh,
    const __nv_bfloat16* __restrict__ wl, int k0, int tid)
{
#pragma unroll
    for (int t = 0; t < 2; t++) {
        int op = tid + t * 256;
        int r  = op >> 2;
        int ch = op & 3;
        uint32_t doff = (uint32_t)(r * ROW_B + ch * 16);
        size_t soff = (size_t)r * T_DIM + k0 + ch * 8;
        cp16(st + OFF_AH + doff, xh + soff);
        cp16(st + OFF_AL + doff, xl + soff);
        cp16(st + OFF_BH + doff, wh + soff);
        cp16(st + OFF_BL + doff, wl + soff);
    }
}

__global__ void __launch_bounds__(256, 2) gemm_mma(
    const float* __restrict__ bq, const float* __restrict__ bk,
    const float* __restrict__ bv)
{
    extern __shared__ __align__(16) char dyn[];

    const int tid  = threadIdx.x;
    const int lane = tid & 31;
    const int wid  = tid >> 5;
    const int mat  = blockIdx.x >> 1;
    const int bn   = blockIdx.x & 1;
    const int bm   = blockIdx.y;

    const int wm = (wid >> 2) * 64;
    const int wn = (wid & 3) * 32;

    const __nv_bfloat16* xh = g_xh + (size_t)bm * 128 * T_DIM;
    const __nv_bfloat16* xl = g_xl + (size_t)bm * 128 * T_DIM;
    const __nv_bfloat16* wh = g_wh + ((size_t)mat * 256 + bn * 128) * T_DIM;
    const __nv_bfloat16* wl = g_wl + ((size_t)mat * 256 + bn * 128) * T_DIM;
    const float* bias = (mat == 0) ? bq : (mat == 1) ? bk : bv;
    __nv_bfloat16* outh = ((mat == 0) ? g_qh : (mat == 1) ? g_kh : g_vh)
                          + (size_t)bm * 128 * 256 + bn * 128;
    __nv_bfloat16* outl = ((mat == 0) ? g_ql : (mat == 1) ? g_kl : g_vl)
                          + (size_t)bm * 128 * 256 + bn * 128;

    const uint32_t sbase = smem_u32(dyn);

    float acc[4][4][4];
#pragma unroll
    for (int i = 0; i < 4; i++)
#pragma unroll
        for (int j = 0; j < 4; j++)
#pragma unroll
            for (int r = 0; r < 4; r++) acc[i][j][r] = 0.0f;

    const uint32_t aoff = (uint32_t)((wm + (lane & 15)) * ROW_B + (lane >> 4) * 16);
    const uint32_t boff = (uint32_t)((wn + ((lane >> 4) << 3) + (lane & 7)) * ROW_B
                                     + ((lane >> 3) & 1) * 16);

    load_chunk(sbase + 0 * STAGE_B, xh, xl, wh, wl, 0, tid);
    CP_COMMIT();
    load_chunk(sbase + 1 * STAGE_B, xh, xl, wh, wl, 32, tid);
    CP_COMMIT();

    for (int c = 0; c < NCHUNK; c++) {
        const uint32_t st = sbase + (c & 1) * STAGE_B;
        CP_WAIT1();
        __syncthreads();

#pragma unroll
        for (int ks = 0; ks < 2; ks++) {
            const uint32_t kadd = (uint32_t)(ks * 32);
            uint32_t ah[4][4], bh[2][4];
#pragma unroll
            for (int mi = 0; mi < 4; mi++)
                ldsm4(ah[mi], st + OFF_AH + aoff + mi * (16 * ROW_B) + kadd);
#pragma unroll
            for (int np = 0; np < 2; np++)
                ldsm4(bh[np], st + OFF_BH + boff + np * (16 * ROW_B) + kadd);
#pragma unroll
            for (int mi = 0; mi < 4; mi++)
#pragma unroll
                for (int nj = 0; nj < 4; nj++)
                    mma16816(acc[mi][nj], ah[mi], bh[nj >> 1][(nj & 1) * 2],
                             bh[nj >> 1][(nj & 1) * 2 + 1]);

            uint32_t bl[2][4];
#pragma unroll
            for (int np = 0; np < 2; np++)
                ldsm4(bl[np], st + OFF_BL + boff + np * (16 * ROW_B) + kadd);
#pragma unroll
            for (int mi = 0; mi < 4; mi++)
#pragma unroll
                for (int nj = 0; nj < 4; nj++)
                    mma16816(acc[mi][nj], ah[mi], bl[nj >> 1][(nj & 1) * 2],
                             bl[nj >> 1][(nj & 1) * 2 + 1]);

            uint32_t al[4][4];
#pragma unroll
            for (int mi = 0; mi < 4; mi++)
                ldsm4(al[mi], st + OFF_AL + aoff + mi * (16 * ROW_B) + kadd);
#pragma unroll
            for (int mi = 0; mi < 4; mi++)
#pragma unroll
                for (int nj = 0; nj < 4; nj++)
                    mma16816(acc[mi][nj], al[mi], bh[nj >> 1][(nj & 1) * 2],
                             bh[nj >> 1][(nj & 1) * 2 + 1]);
        }

        __syncthreads();
        if (c + 2 < NCHUNK)
            load_chunk(st, xh, xl, wh, wl, (c + 2) * 32, tid);
        CP_COMMIT();
    }

    const int rq = lane >> 2;
    const int cq = (lane & 3) * 2;
#pragma unroll
    for (int nj = 0; nj < 4; nj++) {
        const int col = wn + nj * 8 + cq;
        const float b0 = bias[bn * 128 + col];
        const float b1 = bias[bn * 128 + col + 1];
#pragma unroll
        for (int mi = 0; mi < 4; mi++) {
            const int row = wm + mi * 16 + rq;
#pragma unroll
            for (int half = 0; half < 2; half++) {
                const float v0 = acc[mi][nj][half * 2 + 0] + b0;
                const float v1 = acc[mi][nj][half * 2 + 1] + b1;
                __nv_bfloat16 h0 = __float2bfloat16(v0);
                __nv_bfloat16 h1 = __float2bfloat16(v1);
                __nv_bfloat16 l0 = __float2bfloat16(v0 - __bfloat162float(h0));
                __nv_bfloat16 l1 = __float2bfloat16(v1 - __bfloat162float(h1));
                const size_t off = (size_t)(row + half * 8) * 256 + col;
                *(uint32_t*)(outh + off) = pack_bf2(h0, h1);
                *(uint32_t*)(outl + off) = pack_bf2(l0, l1);
            }
        }
    }
}

// ---------------------------------------------------------------------------
// Tensor-core attention (R10-exact + dead-barrier removal): 2 CTAs/SM,
// register softmax, phase-2 in two 128-col halves, full 3-pass splits.
// ---------------------------------------------------------------------------
#define P1_ROWB  80
#define P1_TILE  (128 * P1_ROWB)
#define P1_QH    0
#define P1_QL    (1 * P1_TILE)
#define P1_KH    (2 * P1_TILE)
#define P1_KL    (3 * P1_TILE)
#define P1_STAGE (4 * P1_TILE)          // 40960
#define R1_SIZE  (2 * P1_STAGE)         // 81920

#define S_PITCH  136
#define SH_OFF   0
#define SL_OFF   (128 * S_PITCH * 2)    // 34816

#define RB_OFF   R1_SIZE
#define BUFMAX_OFF RB_OFF
#define BUFSUM_OFF (RB_OFF + 2048)
#define V_OFF    (RB_OFF + 4096)
#define V2_PITCHB 272
#define V2_TILE  (16 * V2_PITCHB)       // 4352
#define V2_STAGE (2 * V2_TILE)          // 8704
#define ATTN_SMEM (V_OFF + 2 * V2_STAGE)   // 103424

__device__ __forceinline__ void p1_load(
    uint32_t st, const __nv_bfloat16* __restrict__ qh,
    const __nv_bfloat16* __restrict__ ql,
    const __nv_bfloat16* __restrict__ kh,
    const __nv_bfloat16* __restrict__ kl, int k0, int tid)
{
#pragma unroll
    for (int t = 0; t < 2; t++) {
        int op = tid + t * 256;
        int r  = op >> 2;
        int ch = op & 3;
        uint32_t doff = (uint32_t)(r * P1_ROWB + ch * 16);
        size_t soff = (size_t)r * N_QK + k0 + ch * 8;
        cp16(st + P1_QH + doff, qh + soff);
        cp16(st + P1_QL + doff, ql + soff);
        cp16(st + P1_KH + doff, kh + soff);
        cp16(st + P1_KL + doff, kl + soff);
    }
}

__device__ __forceinline__ void v_load2(
    uint32_t st, const __nv_bfloat16* __restrict__ vh,
    const __nv_bfloat16* __restrict__ vl, int k0, int h, int tid)
{
    int r  = tid >> 4;
    int ch = tid & 15;
    uint32_t doff = (uint32_t)(r * V2_PITCHB + ch * 16);
    size_t soff = (size_t)(k0 + r) * N_V + h * 128 + ch * 8;
    cp16(st + doff, vh + soff);
    cp16(st + V2_TILE + doff, vl + soff);
}

__global__ void __launch_bounds__(256, 2) attn_tc(float* __restrict__ out)
{
    extern __shared__ __align__(16) char dyn[];
    const uint32_t sb = smem_u32(dyn);

    const int tid  = threadIdx.x;
    const int lane = tid & 31;
    const int wid  = tid >> 5;
    const int bd   = blockIdx.x;

    const __nv_bfloat16* qh = g_qh + (size_t)bd * C_DIM * N_QK;
    const __nv_bfloat16* ql = g_ql + (size_t)bd * C_DIM * N_QK;
    const __nv_bfloat16* kh = g_kh + (size_t)bd * C_DIM * N_QK;
    const __nv_bfloat16* kl = g_kl + (size_t)bd * C_DIM * N_QK;
    const __nv_bfloat16* vh = g_vh + (size_t)bd * C_DIM * N_V;
    const __nv_bfloat16* vl = g_vl + (size_t)bd * C_DIM * N_V;
    float* ob = out + (size_t)bd * C_DIM * N_V;

    const int wm = (wid >> 2) * 64;
    const int wn = (wid & 3) * 32;
    const int rq = lane >> 2;
    const int cq = (lane & 3) * 2;

    float* bufMax = (float*)(dyn + BUFMAX_OFF);
    float* bufSum = (float*)(dyn + BUFSUM_OFF);

    // ================= Phase 1: S = q @ k^T (regs, 3-pass split) ==========
    float acc[4][4][4];
#pragma unroll
    for (int i = 0; i < 4; i++)
#pragma unroll
        for (int j = 0; j < 4; j++)
#pragma unroll
            for (int r = 0; r < 4; r++) acc[i][j][r] = 0.0f;

    {
        const uint32_t aoff = (uint32_t)((wm + (lane & 15)) * P1_ROWB + (lane >> 4) * 16);
        const uint32_t boff = (uint32_t)((wn + ((lane >> 4) << 3) + (lane & 7)) * P1_ROWB
                                         + ((lane >> 3) & 1) * 16);

        p1_load(sb + 0 * P1_STAGE, qh, ql, kh, kl, 0, tid);
        CP_COMMIT();
        p1_load(sb + 1 * P1_STAGE, qh, ql, kh, kl, 32, tid);
        CP_COMMIT();

        for (int c = 0; c < 8; c++) {
            const uint32_t st = sb + (c & 1) * P1_STAGE;
            CP_WAIT1();
            __syncthreads();

#pragma unroll
            for (int ks = 0; ks < 2; ks++) {
                const uint32_t kadd = (uint32_t)(ks * 32);
                uint32_t ah[4][4], bh[2][4];
#pragma unroll
                for (int mi = 0; mi < 4; mi++)
                    ldsm4(ah[mi], st + P1_QH + aoff + mi * (16 * P1_ROWB) + kadd);
#pragma unroll
                for (int np = 0; np < 2; np++)
                    ldsm4(bh[np], st + P1_KH + boff + np * (16 * P1_ROWB) + kadd);
#pragma unroll
                for (int mi = 0; mi < 4; mi++)
#pragma unroll
                    for (int nj = 0; nj < 4; nj++)
                        mma16816(acc[mi][nj], ah[mi], bh[nj >> 1][(nj & 1) * 2],
                                 bh[nj >> 1][(nj & 1) * 2 + 1]);

                uint32_t bl[2][4];
#pragma unroll
                for (int np = 0; np < 2; np++)
                    ldsm4(bl[np], st + P1_KL + boff + np * (16 * P1_ROWB) + kadd);
#pragma unroll
                for (int mi = 0; mi < 4; mi++)
#pragma unroll
                    for (int nj = 0; nj < 4; nj++)
                        mma16816(acc[mi][nj], ah[mi], bl[nj >> 1][(nj & 1) * 2],
                                 bl[nj >> 1][(nj & 1) * 2 + 1]);

                uint32_t al[4][4];
#pragma unroll
                for (int mi = 0; mi < 4; mi++)
                    ldsm4(al[mi], st + P1_QL + aoff + mi * (16 * P1_ROWB) + kadd);
#pragma unroll
                for (int mi = 0; mi < 4; mi++)
#pragma unroll
                    for (int nj = 0; nj < 4; nj++)
                        mma16816(acc[mi][nj], al[mi], bh[nj >> 1][(nj & 1) * 2],
                                 bh[nj >> 1][(nj & 1) * 2 + 1]);
            }

            __syncthreads();
            if (c + 2 < 8)
                p1_load(st, qh, ql, kh, kl, (c + 2) * 32, tid);
            CP_COMMIT();
        }
    }

    // ================= Softmax from registers =================
    {
        const float scale = 0.0625f;
#pragma unroll
        for (int mi = 0; mi < 4; mi++)
#pragma unroll
            for (int nj = 0; nj < 4; nj++)
#pragma unroll
                for (int r = 0; r < 4; r++) acc[mi][nj][r] *= scale;

        float m[4][2];
#pragma unroll
        for (int mi = 0; mi < 4; mi++)
#pragma unroll
            for (int h = 0; h < 2; h++) {
                float v = -1e30f;
#pragma unroll
                for (int nj = 0; nj < 4; nj++) {
                    v = fmaxf(v, acc[mi][nj][h * 2]);
                    v = fmaxf(v, acc[mi][nj][h * 2 + 1]);
                }
                v = fmaxf(v, __shfl_xor_sync(0xffffffffu, v, 1));
                v = fmaxf(v, __shfl_xor_sync(0xffffffffu, v, 2));
                m[mi][h] = v;
            }
        if ((lane & 3) == 0) {
#pragma unroll
            for (int mi = 0; mi < 4; mi++)
#pragma unroll
                for (int h = 0; h < 2; h++) {
                    int row = wm + mi * 16 + rq + h * 8;
                    bufMax[row * 4 + (wid & 3)] = m[mi][h];
                }
        }
        __syncthreads();

        float Mx[4][2];
#pragma unroll
        for (int mi = 0; mi < 4; mi++)
#pragma unroll
            for (int h = 0; h < 2; h++) {
                int row = wm + mi * 16 + rq + h * 8;
                float a0 = bufMax[row * 4 + 0], a1 = bufMax[row * 4 + 1];
                float a2 = bufMax[row * 4 + 2], a3 = bufMax[row * 4 + 3];
                Mx[mi][h] = fmaxf(fmaxf(a0, a1), fmaxf(a2, a3));
            }

        float s[4][2];
#pragma unroll
        for (int mi = 0; mi < 4; mi++)
#pragma unroll
            for (int h = 0; h < 2; h++) {
                float v = 0.0f;
#pragma unroll
                for (int nj = 0; nj < 4; nj++) {
                    float e0 = __expf(acc[mi][nj][h * 2]     - Mx[mi][h]);
                    float e1 = __expf(acc[mi][nj][h * 2 + 1] - Mx[mi][h]);
                    acc[mi][nj][h * 2]     = e0;
                    acc[mi][nj][h * 2 + 1] = e1;
                    v += e0 + e1;
                }
                v += __shfl_xor_sync(0xffffffffu, v, 1);
                v += __shfl_xor_sync(0xffffffffu, v, 2);
                s[mi][h] = v;
            }
        if ((lane & 3) == 0) {
#pragma unroll
            for (int mi = 0; mi < 4; mi++)
#pragma unroll
                for (int h = 0; h < 2; h++) {
                    int row = wm + mi * 16 + rq + h * 8;
                    bufSum[row * 4 + (wid & 3)] = s[mi][h];
                }
        }
        __syncthreads();

#pragma unroll
        for (int mi = 0; mi < 4; mi++)
#pragma unroll
            for (int h = 0; h < 2; h++) {
                int row = wm + mi * 16 + rq + h * 8;
                float inv = 1.0f / (bufSum[row * 4 + 0] + bufSum[row * 4 + 1]
                                  + bufSum[row * 4 + 2] + bufSum[row * 4 + 3]);
#pragma unroll
                for (int nj = 0; nj < 4; nj++) {
                    int col = wn + nj * 8 + cq;
                    float f0 = acc[mi][nj][h * 2]     * inv;
                    float f1 = acc[mi][nj][h * 2 + 1] * inv;
                    __nv_bfloat16 h0 = __float2bfloat16(f0);
                    __nv_bfloat16 h1 = __float2bfloat16(f1);
                    __nv_bfloat16 l0 = __float2bfloat16(f0 - __bfloat162float(h0));
                    __nv_bfloat16 l1 = __float2bfloat16(f1 - __bfloat162float(h1));
                    uint32_t off = (uint32_t)(row * S_PITCH + col) * 2;
                    *(uint32_t*)(dyn + SH_OFF + off) = pack_bf2(h0, h1);
                    *(uint32_t*)(dyn + SL_OFF + off) = pack_bf2(l0, l1);
                }
            }
    }
    __syncthreads();

    // ================= Phase 2: Z = S @ V, two 128-col halves =================
    const uint32_t aoff2 = (uint32_t)((wm + (lane & 15)) * (S_PITCH * 2)
                                      + (lane >> 4) * 16);
    const uint32_t bro = (uint32_t)((lane & 15) * V2_PITCHB + (lane >> 4) * 16);
    const int wn2 = (wid & 3) * 32;

#pragma unroll
    for (int h = 0; h < 2; h++) {
        float acc2[4][4][4];
#pragma unroll
        for (int i = 0; i < 4; i++)
#pragma unroll
            for (int j = 0; j < 4; j++)
#pragma unroll
                for (int r = 0; r < 4; r++) acc2[i][j][r] = 0.0f;

        v_load2(sb + V_OFF + 0 * V2_STAGE, vh, vl, 0, h, tid);
        CP_COMMIT();
        v_load2(sb + V_OFF + 1 * V2_STAGE, vh, vl, 16, h, tid);
        CP_COMMIT();

        for (int c = 0; c < 8; c++) {
            const uint32_t st = sb + V_OFF + (c & 1) * V2_STAGE;
            CP_WAIT1();
            __syncthreads();

            const uint32_t acol = (uint32_t)(c * 32);

            uint32_t ah[4][4], bh[2][4];
#pragma unroll
            for (int mi = 0; mi < 4; mi++)
                ldsm4(ah[mi], sb + SH_OFF + aoff2 + mi * (16 * S_PITCH * 2) + acol);
#pragma unroll
            for (int nb = 0; nb < 2; nb++)
                ldsm4t(bh[nb], st + bro + (uint32_t)((wn2 + nb * 16) * 2));
#pragma unroll
            for (int mi = 0; mi < 4; mi++)
#pragma unroll
                for (int nj = 0; nj < 4; nj++)
                    mma16816(acc2[mi][nj], ah[mi], bh[nj >> 1][(nj & 1) * 2],
                             bh[nj >> 1][(nj & 1) * 2 + 1]);

            uint32_t bl[2][4];
#pragma unroll
            for (int nb = 0; nb < 2; nb++)
                ldsm4t(bl[nb], st + V2_TILE + bro + (uint32_t)((wn2 + nb * 16) * 2));
#pragma unroll
            for (int mi = 0; mi < 4; mi++)
#pragma unroll
                for (int nj = 0; nj < 4; nj++)
                    mma16816(acc2[mi][nj], ah[mi], bl[nj >> 1][(nj & 1) * 2],
                             bl[nj >> 1][(nj & 1) * 2 + 1]);

            uint32_t al[4][4];
#pragma unroll
            for (int mi = 0; mi < 4; mi++)
                ldsm4(al[mi], sb + SL_OFF + aoff2 + mi * (16 * S_PITCH * 2) + acol);
#pragma unroll
            for (int mi = 0; mi < 4; mi++)
#pragma unroll
                for (int nj = 0; nj < 4; nj++)
                    mma16816(acc2[mi][nj], al[mi], bh[nj >> 1][(nj & 1) * 2],
                             bh[nj >> 1][(nj & 1) * 2 + 1]);

            __syncthreads();
            if (c + 2 < 8)
                v_load2(st, vh, vl, (c + 2) * 16, h, tid);
            CP_COMMIT();
        }

#pragma unroll
        for (int nj = 0; nj < 4; nj++) {
            const int col = h * 128 + wn2 + nj * 8 + cq;
#pragma unroll
            for (int mi = 0; mi < 4; mi++) {
                const int row = wm + mi * 16 + rq;
                *(float2*)(ob + (size_t)row * N_V + col) =
                    make_float2(acc2[mi][nj][0], acc2[mi][nj][1]);
                *(float2*)(ob + (size_t)(row + 8) * N_V + col) =
                    make_float2(acc2[mi][nj][2], acc2[mi][nj][3]);
            }
        }
        if (h == 0) __syncthreads();   // stage reuse guard; dead after h=1
    }
}

// ---------------------------------------------------------------------------
extern "C" void kernel_launch(void* const* d_in, const int* in_sizes, int n_in,
                              void* d_out, int out_size)
{
    const float* x  = (const float*)d_in[0];
    const float* Wq = (const float*)d_in[1];
    const float* bq = (const float*)d_in[2];
    const float* Wk = (const float*)d_in[3];
    const float* bk = (const float*)d_in[4];
    const float* Wv = (const float*)d_in[5];
    const float* bv = (const float*)d_in[6];
    float* out = (float*)d_out;

    conv_x<<<4096, 256>>>(x);
    conv_w<<<dim3(64, 3), 256>>>(Wq, Wk, Wv);

    cudaFuncSetAttribute(gemm_mma, cudaFuncAttributeMaxDynamicSharedMemorySize,
                         GEMM_SMEM);
    gemm_mma<<<dim3(6, 1024), 256, GEMM_SMEM>>>(bq, bk, bv);

    cudaFuncSetAttribute(attn_tc, cudaFuncAttributeMaxDynamicSharedMemorySize,
                         ATTN_SMEM);
    attn_tc<<<BD, 256, ATTN_SMEM>>>(out);
}

// round 17
// speedup vs baseline: 1.0825x; 1.0027x over previous
#include <cuda_runtime.h>
#include <cuda_bf16.h>
#include <cstdint>

// Problem constants
#define T_DIM 1024
#define N_QK  256
#define N_V   256
#define C_DIM 128
#define BD    1024
#define M_TOT (BD * C_DIM)   // 131072

// ---------------------------------------------------------------------------
// Scratch (__device__ globals; alloc-free rule)
// ---------------------------------------------------------------------------
__device__ __align__(16) __nv_bfloat16 g_qh[(size_t)M_TOT * N_QK];
__device__ __align__(16) __nv_bfloat16 g_ql[(size_t)M_TOT * N_QK];
__device__ __align__(16) __nv_bfloat16 g_kh[(size_t)M_TOT * N_QK];
__device__ __align__(16) __nv_bfloat16 g_kl[(size_t)M_TOT * N_QK];
__device__ __align__(16) __nv_bfloat16 g_vh[(size_t)M_TOT * N_V];
__device__ __align__(16) __nv_bfloat16 g_vl[(size_t)M_TOT * N_V];

__device__ __align__(16) __nv_bfloat16 g_xh[(size_t)M_TOT * T_DIM];
__device__ __align__(16) __nv_bfloat16 g_xl[(size_t)M_TOT * T_DIM];
__device__ __align__(16) __nv_bfloat16 g_wh[3 * 256 * T_DIM];
__device__ __align__(16) __nv_bfloat16 g_wl[3 * 256 * T_DIM];

// ---------------------------------------------------------------------------
// Helpers
// ---------------------------------------------------------------------------
__device__ __forceinline__ uint32_t smem_u32(const void* p) {
    uint32_t a;
    asm("{ .reg .u64 t; cvta.to.shared.u64 t, %1; cvt.u32.u64 %0, t; }"
        : "=r"(a) : "l"(p));
    return a;
}
__device__ __forceinline__ void cp16(uint32_t dst, const void* src) {
    asm volatile("cp.async.cg.shared.global [%0], [%1], 16;"
                 :: "r"(dst), "l"(src) : "memory");
}
#define CP_COMMIT() asm volatile("cp.async.commit_group;" ::: "memory")
#define CP_WAIT1()  asm volatile("cp.async.wait_group 1;" ::: "memory")

__device__ __forceinline__ void ldsm4(uint32_t* r, uint32_t addr) {
    asm volatile("ldmatrix.sync.aligned.m8n8.x4.shared.b16 {%0,%1,%2,%3}, [%4];"
                 : "=r"(r[0]), "=r"(r[1]), "=r"(r[2]), "=r"(r[3]) : "r"(addr));
}
__device__ __forceinline__ void ldsm4t(uint32_t* r, uint32_t addr) {
    asm volatile("ldmatrix.sync.aligned.m8n8.x4.trans.shared.b16 {%0,%1,%2,%3}, [%4];"
                 : "=r"(r[0]), "=r"(r[1]), "=r"(r[2]), "=r"(r[3]) : "r"(addr));
}
__device__ __forceinline__ void mma16816(float* d, const uint32_t* a,
                                         uint32_t b0, uint32_t b1) {
    asm volatile(
        "mma.sync.aligned.m16n8k16.row.col.f32.bf16.bf16.f32 "
        "{%0,%1,%2,%3}, {%4,%5,%6,%7}, {%8,%9}, {%0,%1,%2,%3};"
        : "+f"(d[0]), "+f"(d[1]), "+f"(d[2]), "+f"(d[3])
        : "r"(a[0]), "r"(a[1]), "r"(a[2]), "r"(a[3]), "r"(b0), "r"(b1));
}
__device__ __forceinline__ uint32_t pack_bf2(__nv_bfloat16 a, __nv_bfloat16 b) {
    return (uint32_t)__bfloat16_as_ushort(a) | ((uint32_t)__bfloat16_as_ushort(b) << 16);
}

// ---------------------------------------------------------------------------
// Fused convert kernel: blocks [0,4096) split X; blocks [4096,4288) split W.
// Same arithmetic as the previous conv_x / conv_w (bit-identical outputs).
// ---------------------------------------------------------------------------
#define CONVX_BLOCKS 4096
#define CONVW_BLOCKS 192   // 3 mats x 64

__global__ void __launch_bounds__(256) conv_all(
    const float* __restrict__ x,
    const float* __restrict__ Wq, const float* __restrict__ Wk,
    const float* __restrict__ Wv)
{
    if (blockIdx.x < CONVX_BLOCKS) {
        const size_t n4 = (size_t)M_TOT * T_DIM / 4;
        const size_t stride = (size_t)CONVX_BLOCKS * blockDim.x;
        uint2* __restrict__ xh = (uint2*)g_xh;
        uint2* __restrict__ xl = (uint2*)g_xl;
        for (size_t i = (size_t)blockIdx.x * blockDim.x + threadIdx.x; i < n4;
             i += stride) {
            float4 f = ((const float4*)x)[i];
            __nv_bfloat16 h0 = __float2bfloat16(f.x);
            __nv_bfloat16 h1 = __float2bfloat16(f.y);
            __nv_bfloat16 h2 = __float2bfloat16(f.z);
            __nv_bfloat16 h3 = __float2bfloat16(f.w);
            __nv_bfloat16 l0 = __float2bfloat16(f.x - __bfloat162float(h0));
            __nv_bfloat16 l1 = __float2bfloat16(f.y - __bfloat162float(h1));
            __nv_bfloat16 l2 = __float2bfloat16(f.z - __bfloat162float(h2));
            __nv_bfloat16 l3 = __float2bfloat16(f.w - __bfloat162float(h3));
            xh[i] = make_uint2(pack_bf2(h0, h1), pack_bf2(h2, h3));
            xl[i] = make_uint2(pack_bf2(l0, l1), pack_bf2(l2, l3));
        }
    } else {
        const int wb  = blockIdx.x - CONVX_BLOCKS;   // 0..191
        const int mat = wb / 64;                      // 0..2
        const int bx  = wb % 64;
        const float* W = (mat == 0) ? Wq : (mat == 1) ? Wk : Wv;
        const size_t n4 = 256 * T_DIM / 4;
        const size_t base = (size_t)mat * n4;
        uint2* __restrict__ wh = (uint2*)g_wh;
        uint2* __restrict__ wl = (uint2*)g_wl;
        for (size_t i = (size_t)bx * blockDim.x + threadIdx.x; i < n4;
             i += (size_t)64 * blockDim.x) {
            float4 f = ((const float4*)W)[i];
            __nv_bfloat16 h0 = __float2bfloat16(f.x);
            __nv_bfloat16 h1 = __float2bfloat16(f.y);
            __nv_bfloat16 h2 = __float2bfloat16(f.z);
            __nv_bfloat16 h3 = __float2bfloat16(f.w);
            __nv_bfloat16 l0 = __float2bfloat16(f.x - __bfloat162float(h0));
            __nv_bfloat16 l1 = __float2bfloat16(f.y - __bfloat162float(h1));
            __nv_bfloat16 l2 = __float2bfloat16(f.z - __bfloat162float(h2));
            __nv_bfloat16 l3 = __float2bfloat16(f.w - __bfloat162float(h3));
            wh[base + i] = make_uint2(pack_bf2(h0, h1), pack_bf2(h2, h3));
            wl[base + i] = make_uint2(pack_bf2(l0, l1), pack_bf2(l2, l3));
        }
    }
}

// ---------------------------------------------------------------------------
// HMMA GEMM (R10-exact): 128x128 CTA tile, 256 thr (8 warps, 2x4), 64x32
// warp tile, BK=32, 2 stages, 2 CTAs/SM.
// ---------------------------------------------------------------------------
#define ROW_B   80
#define TILE_B  (128 * ROW_B)
#define OFF_AH  0
#define OFF_AL  (1 * TILE_B)
#define OFF_BH  (2 * TILE_B)
#define OFF_BL  (3 * TILE_B)
#define STAGE_B (4 * TILE_B)
#define GEMM_SMEM (2 * STAGE_B)
#define NCHUNK  32

__device__ __forceinline__ void load_chunk(
    uint32_t st, const __nv_bfloat16* __restrict__ xh,
    const __nv_bfloat16* __restrict__ xl,
    const __nv_bfloat16* __restrict__ wh,
    const __nv_bfloat16* __restrict__ wl, int k0, int tid)
{
#pragma unroll
    for (int t = 0; t < 2; t++) {
        int op = tid + t * 256;
        int r  = op >> 2;
        int ch = op & 3;
        uint32_t doff = (uint32_t)(r * ROW_B + ch * 16);
        size_t soff = (size_t)r * T_DIM + k0 + ch * 8;
        cp16(st + OFF_AH + doff, xh + soff);
        cp16(st + OFF_AL + doff, xl + soff);
        cp16(st + OFF_BH + doff, wh + soff);
        cp16(st + OFF_BL + doff, wl + soff);
    }
}

__global__ void __launch_bounds__(256, 2) gemm_mma(
    const float* __restrict__ bq, const float* __restrict__ bk,
    const float* __restrict__ bv)
{
    extern __shared__ __align__(16) char dyn[];

    const int tid  = threadIdx.x;
    const int lane = tid & 31;
    const int wid  = tid >> 5;
    const int mat  = blockIdx.x >> 1;
    const int bn   = blockIdx.x & 1;
    const int bm   = blockIdx.y;

    const int wm = (wid >> 2) * 64;
    const int wn = (wid & 3) * 32;

    const __nv_bfloat16* xh = g_xh + (size_t)bm * 128 * T_DIM;
    const __nv_bfloat16* xl = g_xl + (size_t)bm * 128 * T_DIM;
    const __nv_bfloat16* wh = g_wh + ((size_t)mat * 256 + bn * 128) * T_DIM;
    const __nv_bfloat16* wl = g_wl + ((size_t)mat * 256 + bn * 128) * T_DIM;
    const float* bias = (mat == 0) ? bq : (mat == 1) ? bk : bv;
    __nv_bfloat16* outh = ((mat == 0) ? g_qh : (mat == 1) ? g_kh : g_vh)
                          + (size_t)bm * 128 * 256 + bn * 128;
    __nv_bfloat16* outl = ((mat == 0) ? g_ql : (mat == 1) ? g_kl : g_vl)
                          + (size_t)bm * 128 * 256 + bn * 128;

    const uint32_t sbase = smem_u32(dyn);

    float acc[4][4][4];
#pragma unroll
    for (int i = 0; i < 4; i++)
#pragma unroll
        for (int j = 0; j < 4; j++)
#pragma unroll
            for (int r = 0; r < 4; r++) acc[i][j][r] = 0.0f;

    const uint32_t aoff = (uint32_t)((wm + (lane & 15)) * ROW_B + (lane >> 4) * 16);
    const uint32_t boff = (uint32_t)((wn + ((lane >> 4) << 3) + (lane & 7)) * ROW_B
                                     + ((lane >> 3) & 1) * 16);

    load_chunk(sbase + 0 * STAGE_B, xh, xl, wh, wl, 0, tid);
    CP_COMMIT();
    load_chunk(sbase + 1 * STAGE_B, xh, xl, wh, wl, 32, tid);
    CP_COMMIT();

    for (int c = 0; c < NCHUNK; c++) {
        const uint32_t st = sbase + (c & 1) * STAGE_B;
        CP_WAIT1();
        __syncthreads();

#pragma unroll
        for (int ks = 0; ks < 2; ks++) {
            const uint32_t kadd = (uint32_t)(ks * 32);
            uint32_t ah[4][4], bh[2][4];
#pragma unroll
            for (int mi = 0; mi < 4; mi++)
                ldsm4(ah[mi], st + OFF_AH + aoff + mi * (16 * ROW_B) + kadd);
#pragma unroll
            for (int np = 0; np < 2; np++)
                ldsm4(bh[np], st + OFF_BH + boff + np * (16 * ROW_B) + kadd);
#pragma unroll
            for (int mi = 0; mi < 4; mi++)
#pragma unroll
                for (int nj = 0; nj < 4; nj++)
                    mma16816(acc[mi][nj], ah[mi], bh[nj >> 1][(nj & 1) * 2],
                             bh[nj >> 1][(nj & 1) * 2 + 1]);

            uint32_t bl[2][4];
#pragma unroll
            for (int np = 0; np < 2; np++)
                ldsm4(bl[np], st + OFF_BL + boff + np * (16 * ROW_B) + kadd);
#pragma unroll
            for (int mi = 0; mi < 4; mi++)
#pragma unroll
                for (int nj = 0; nj < 4; nj++)
                    mma16816(acc[mi][nj], ah[mi], bl[nj >> 1][(nj & 1) * 2],
                             bl[nj >> 1][(nj & 1) * 2 + 1]);

            uint32_t al[4][4];
#pragma unroll
            for (int mi = 0; mi < 4; mi++)
                ldsm4(al[mi], st + OFF_AL + aoff + mi * (16 * ROW_B) + kadd);
#pragma unroll
            for (int mi = 0; mi < 4; mi++)
#pragma unroll
                for (int nj = 0; nj < 4; nj++)
                    mma16816(acc[mi][nj], al[mi], bh[nj >> 1][(nj & 1) * 2],
                             bh[nj >> 1][(nj & 1) * 2 + 1]);
        }

        __syncthreads();
        if (c + 2 < NCHUNK)
            load_chunk(st, xh, xl, wh, wl, (c + 2) * 32, tid);
        CP_COMMIT();
    }

    const int rq = lane >> 2;
    const int cq = (lane & 3) * 2;
#pragma unroll
    for (int nj = 0; nj < 4; nj++) {
        const int col = wn + nj * 8 + cq;
        const float b0 = bias[bn * 128 + col];
        const float b1 = bias[bn * 128 + col + 1];
#pragma unroll
        for (int mi = 0; mi < 4; mi++) {
            const int row = wm + mi * 16 + rq;
#pragma unroll
            for (int half = 0; half < 2; half++) {
                const float v0 = acc[mi][nj][half * 2 + 0] + b0;
                const float v1 = acc[mi][nj][half * 2 + 1] + b1;
                __nv_bfloat16 h0 = __float2bfloat16(v0);
                __nv_bfloat16 h1 = __float2bfloat16(v1);
                __nv_bfloat16 l0 = __float2bfloat16(v0 - __bfloat162float(h0));
                __nv_bfloat16 l1 = __float2bfloat16(v1 - __bfloat162float(h1));
                const size_t off = (size_t)(row + half * 8) * 256 + col;
                *(uint32_t*)(outh + off) = pack_bf2(h0, h1);
                *(uint32_t*)(outl + off) = pack_bf2(l0, l1);
            }
        }
    }
}

// ---------------------------------------------------------------------------
// Tensor-core attention (R10 + h=0 V-prologue hoisted above softmax):
// 2 CTAs/SM, register softmax, phase-2 in two 128-col halves, 3-pass splits.
// ---------------------------------------------------------------------------
#define P1_ROWB  80
#define P1_TILE  (128 * P1_ROWB)
#define P1_QH    0
#define P1_QL    (1 * P1_TILE)
#define P1_KH    (2 * P1_TILE)
#define P1_KL    (3 * P1_TILE)
#define P1_STAGE (4 * P1_TILE)          // 40960
#define R1_SIZE  (2 * P1_STAGE)         // 81920

#define S_PITCH  136
#define SH_OFF   0
#define SL_OFF   (128 * S_PITCH * 2)    // 34816

#define RB_OFF   R1_SIZE
#define BUFMAX_OFF RB_OFF
#define BUFSUM_OFF (RB_OFF + 2048)
#define V_OFF    (RB_OFF + 4096)
#define V2_PITCHB 272
#define V2_TILE  (16 * V2_PITCHB)       // 4352
#define V2_STAGE (2 * V2_TILE)          // 8704
#define ATTN_SMEM (V_OFF + 2 * V2_STAGE)   // 103424

__device__ __forceinline__ void p1_load(
    uint32_t st, const __nv_bfloat16* __restrict__ qh,
    const __nv_bfloat16* __restrict__ ql,
    const __nv_bfloat16* __restrict__ kh,
    const __nv_bfloat16* __restrict__ kl, int k0, int tid)
{
#pragma unroll
    for (int t = 0; t < 2; t++) {
        int op = tid + t * 256;
        int r  = op >> 2;
        int ch = op & 3;
        uint32_t doff = (uint32_t)(r * P1_ROWB + ch * 16);
        size_t soff = (size_t)r * N_QK + k0 + ch * 8;
        cp16(st + P1_QH + doff, qh + soff);
        cp16(st + P1_QL + doff, ql + soff);
        cp16(st + P1_KH + doff, kh + soff);
        cp16(st + P1_KL + doff, kl + soff);
    }
}

__device__ __forceinline__ void v_load2(
    uint32_t st, const __nv_bfloat16* __restrict__ vh,
    const __nv_bfloat16* __restrict__ vl, int k0, int h, int tid)
{
    int r  = tid >> 4;
    int ch = tid & 15;
    uint32_t doff = (uint32_t)(r * V2_PITCHB + ch * 16);
    size_t soff = (size_t)(k0 + r) * N_V + h * 128 + ch * 8;
    cp16(st + doff, vh + soff);
    cp16(st + V2_TILE + doff, vl + soff);
}

__global__ void __launch_bounds__(256, 2) attn_tc(float* __restrict__ out)
{
    extern __shared__ __align__(16) char dyn[];
    const uint32_t sb = smem_u32(dyn);

    const int tid  = threadIdx.x;
    const int lane = tid & 31;
    const int wid  = tid >> 5;
    const int bd   = blockIdx.x;

    const __nv_bfloat16* qh = g_qh + (size_t)bd * C_DIM * N_QK;
    const __nv_bfloat16* ql = g_ql + (size_t)bd * C_DIM * N_QK;
    const __nv_bfloat16* kh = g_kh + (size_t)bd * C_DIM * N_QK;
    const __nv_bfloat16* kl = g_kl + (size_t)bd * C_DIM * N_QK;
    const __nv_bfloat16* vh = g_vh + (size_t)bd * C_DIM * N_V;
    const __nv_bfloat16* vl = g_vl + (size_t)bd * C_DIM * N_V;
    float* ob = out + (size_t)bd * C_DIM * N_V;

    const int wm = (wid >> 2) * 64;
    const int wn = (wid & 3) * 32;
    const int rq = lane >> 2;
    const int cq = (lane & 3) * 2;

    float* bufMax = (float*)(dyn + BUFMAX_OFF);
    float* bufSum = (float*)(dyn + BUFSUM_OFF);

    // ================= Phase 1: S = q @ k^T (regs, 3-pass split) ==========
    float acc[4][4][4];
#pragma unroll
    for (int i = 0; i < 4; i++)
#pragma unroll
        for (int j = 0; j < 4; j++)
#pragma unroll
            for (int r = 0; r < 4; r++) acc[i][j][r] = 0.0f;

    {
        const uint32_t aoff = (uint32_t)((wm + (lane & 15)) * P1_ROWB + (lane >> 4) * 16);
        const uint32_t boff = (uint32_t)((wn + ((lane >> 4) << 3) + (lane & 7)) * P1_ROWB
                                         + ((lane >> 3) & 1) * 16);

        p1_load(sb + 0 * P1_STAGE, qh, ql, kh, kl, 0, tid);
        CP_COMMIT();
        p1_load(sb + 1 * P1_STAGE, qh, ql, kh, kl, 32, tid);
        CP_COMMIT();

        for (int c = 0; c < 8; c++) {
            const uint32_t st = sb + (c & 1) * P1_STAGE;
            CP_WAIT1();
            __syncthreads();

#pragma unroll
            for (int ks = 0; ks < 2; ks++) {
                const uint32_t kadd = (uint32_t)(ks * 32);
                uint32_t ah[4][4], bh[2][4];
#pragma unroll
                for (int mi = 0; mi < 4; mi++)
                    ldsm4(ah[mi], st + P1_QH + aoff + mi * (16 * P1_ROWB) + kadd);
#pragma unroll
                for (int np = 0; np < 2; np++)
                    ldsm4(bh[np], st + P1_KH + boff + np * (16 * P1_ROWB) + kadd);
#pragma unroll
                for (int mi = 0; mi < 4; mi++)
#pragma unroll
                    for (int nj = 0; nj < 4; nj++)
                        mma16816(acc[mi][nj], ah[mi], bh[nj >> 1][(nj & 1) * 2],
                                 bh[nj >> 1][(nj & 1) * 2 + 1]);

                uint32_t bl[2][4];
#pragma unroll
                for (int np = 0; np < 2; np++)
                    ldsm4(bl[np], st + P1_KL + boff + np * (16 * P1_ROWB) + kadd);
#pragma unroll
                for (int mi = 0; mi < 4; mi++)
#pragma unroll
                    for (int nj = 0; nj < 4; nj++)
                        mma16816(acc[mi][nj], ah[mi], bl[nj >> 1][(nj & 1) * 2],
                                 bl[nj >> 1][(nj & 1) * 2 + 1]);

                uint32_t al[4][4];
#pragma unroll
                for (int mi = 0; mi < 4; mi++)
                    ldsm4(al[mi], st + P1_QL + aoff + mi * (16 * P1_ROWB) + kadd);
#pragma unroll
                for (int mi = 0; mi < 4; mi++)
#pragma unroll
                    for (int nj = 0; nj < 4; nj++)
                        mma16816(acc[mi][nj], al[mi], bh[nj >> 1][(nj & 1) * 2],
                                 bh[nj >> 1][(nj & 1) * 2 + 1]);
            }

            __syncthreads();
            if (c + 2 < 8)
                p1_load(st, qh, ql, kh, kl, (c + 2) * 32, tid);
            CP_COMMIT();
        }
    }

    // Prefetch phase-2 h=0 V stages NOW — independent of softmax below.
    v_load2(sb + V_OFF + 0 * V2_STAGE, vh, vl, 0, 0, tid);
    CP_COMMIT();
    v_load2(sb + V_OFF + 1 * V2_STAGE, vh, vl, 16, 0, tid);
    CP_COMMIT();

    // ================= Softmax from registers =================
    {
        const float scale = 0.0625f;
#pragma unroll
        for (int mi = 0; mi < 4; mi++)
#pragma unroll
            for (int nj = 0; nj < 4; nj++)
#pragma unroll
                for (int r = 0; r < 4; r++) acc[mi][nj][r] *= scale;

        float m[4][2];
#pragma unroll
        for (int mi = 0; mi < 4; mi++)
#pragma unroll
            for (int h = 0; h < 2; h++) {
                float v = -1e30f;
#pragma unroll
                for (int nj = 0; nj < 4; nj++) {
                    v = fmaxf(v, acc[mi][nj][h * 2]);
                    v = fmaxf(v, acc[mi][nj][h * 2 + 1]);
                }
                v = fmaxf(v, __shfl_xor_sync(0xffffffffu, v, 1));
                v = fmaxf(v, __shfl_xor_sync(0xffffffffu, v, 2));
                m[mi][h] = v;
            }
        if ((lane & 3) == 0) {
#pragma unroll
            for (int mi = 0; mi < 4; mi++)
#pragma unroll
                for (int h = 0; h < 2; h++) {
                    int row = wm + mi * 16 + rq + h * 8;
                    bufMax[row * 4 + (wid & 3)] = m[mi][h];
                }
        }
        __syncthreads();

        float Mx[4][2];
#pragma unroll
        for (int mi = 0; mi < 4; mi++)
#pragma unroll
            for (int h = 0; h < 2; h++) {
                int row = wm + mi * 16 + rq + h * 8;
                float a0 = bufMax[row * 4 + 0], a1 = bufMax[row * 4 + 1];
                float a2 = bufMax[row * 4 + 2], a3 = bufMax[row * 4 + 3];
                Mx[mi][h] = fmaxf(fmaxf(a0, a1), fmaxf(a2, a3));
            }

        float s[4][2];
#pragma unroll
        for (int mi = 0; mi < 4; mi++)
#pragma unroll
            for (int h = 0; h < 2; h++) {
                float v = 0.0f;
#pragma unroll
                for (int nj = 0; nj < 4; nj++) {
                    float e0 = __expf(acc[mi][nj][h * 2]     - Mx[mi][h]);
                    float e1 = __expf(acc[mi][nj][h * 2 + 1] - Mx[mi][h]);
                    acc[mi][nj][h * 2]     = e0;
                    acc[mi][nj][h * 2 + 1] = e1;
                    v += e0 + e1;
                }
                v += __shfl_xor_sync(0xffffffffu, v, 1);
                v += __shfl_xor_sync(0xffffffffu, v, 2);
                s[mi][h] = v;
            }
        if ((lane & 3) == 0) {
#pragma unroll
            for (int mi = 0; mi < 4; mi++)
#pragma unroll
                for (int h = 0; h < 2; h++) {
                    int row = wm + mi * 16 + rq + h * 8;
                    bufSum[row * 4 + (wid & 3)] = s[mi][h];
                }
        }
        __syncthreads();

#pragma unroll
        for (int mi = 0; mi < 4; mi++)
#pragma unroll
            for (int h = 0; h < 2; h++) {
                int row = wm + mi * 16 + rq + h * 8;
                float inv = 1.0f / (bufSum[row * 4 + 0] + bufSum[row * 4 + 1]
                                  + bufSum[row * 4 + 2] + bufSum[row * 4 + 3]);
#pragma unroll
                for (int nj = 0; nj < 4; nj++) {
                    int col = wn + nj * 8 + cq;
                    float f0 = acc[mi][nj][h * 2]     * inv;
                    float f1 = acc[mi][nj][h * 2 + 1] * inv;
                    __nv_bfloat16 h0 = __float2bfloat16(f0);
                    __nv_bfloat16 h1 = __float2bfloat16(f1);
                    __nv_bfloat16 l0 = __float2bfloat16(f0 - __bfloat162float(h0));
                    __nv_bfloat16 l1 = __float2bfloat16(f1 - __bfloat162float(h1));
                    uint32_t off = (uint32_t)(row * S_PITCH + col) * 2;
                    *(uint32_t*)(dyn + SH_OFF + off) = pack_bf2(h0, h1);
                    *(uint32_t*)(dyn + SL_OFF + off) = pack_bf2(l0, l1);
                }
            }
    }
    __syncthreads();

    // ================= Phase 2: Z = S @ V, two 128-col halves =================
    const uint32_t aoff2 = (uint32_t)((wm + (lane & 15)) * (S_PITCH * 2)
                                      + (lane >> 4) * 16);
    const uint32_t bro = (uint32_t)((lane & 15) * V2_PITCHB + (lane >> 4) * 16);
    const int wn2 = (wid & 3) * 32;

#pragma unroll
    for (int h = 0; h < 2; h++) {
        float acc2[4][4][4];
#pragma unroll
        for (int i = 0; i < 4; i++)
#pragma unroll
            for (int j = 0; j < 4; j++)
#pragma unroll
                for (int r = 0; r < 4; r++) acc2[i][j][r] = 0.0f;

        if (h == 1) {
            // h=0 prologue was issued before the softmax
            v_load2(sb + V_OFF + 0 * V2_STAGE, vh, vl, 0, 1, tid);
            CP_COMMIT();
            v_load2(sb + V_OFF + 1 * V2_STAGE, vh, vl, 16, 1, tid);
            CP_COMMIT();
        }

        for (int c = 0; c < 8; c++) {
            const uint32_t st = sb + V_OFF + (c & 1) * V2_STAGE;
            CP_WAIT1();
            __syncthreads();

            const uint32_t acol = (uint32_t)(c * 32);

            uint32_t ah[4][4], bh[2][4];
#pragma unroll
            for (int mi = 0; mi < 4; mi++)
                ldsm4(ah[mi], sb + SH_OFF + aoff2 + mi * (16 * S_PITCH * 2) + acol);
#pragma unroll
            for (int nb = 0; nb < 2; nb++)
                ldsm4t(bh[nb], st + bro + (uint32_t)((wn2 + nb * 16) * 2));
#pragma unroll
            for (int mi = 0; mi < 4; mi++)
#pragma unroll
                for (int nj = 0; nj < 4; nj++)
                    mma16816(acc2[mi][nj], ah[mi], bh[nj >> 1][(nj & 1) * 2],
                             bh[nj >> 1][(nj & 1) * 2 + 1]);

            uint32_t bl[2][4];
#pragma unroll
            for (int nb = 0; nb < 2; nb++)
                ldsm4t(bl[nb], st + V2_TILE + bro + (uint32_t)((wn2 + nb * 16) * 2));
#pragma unroll
            for (int mi = 0; mi < 4; mi++)
#pragma unroll
                for (int nj = 0; nj < 4; nj++)
                    mma16816(acc2[mi][nj], ah[mi], bl[nj >> 1][(nj & 1) * 2],
                             bl[nj >> 1][(nj & 1) * 2 + 1]);

            uint32_t al[4][4];
#pragma unroll
            for (int mi = 0; mi < 4; mi++)
                ldsm4(al[mi], sb + SL_OFF + aoff2 + mi * (16 * S_PITCH * 2) + acol);
#pragma unroll
            for (int mi = 0; mi < 4; mi++)
#pragma unroll
                for (int nj = 0; nj < 4; nj++)
                    mma16816(acc2[mi][nj], al[mi], bh[nj >> 1][(nj & 1) * 2],
                             bh[nj >> 1][(nj & 1) * 2 + 1]);

            __syncthreads();
            if (c + 2 < 8)
                v_load2(st, vh, vl, (c + 2) * 16, h, tid);
            CP_COMMIT();
        }

#pragma unroll
        for (int nj = 0; nj < 4; nj++) {
            const int col = h * 128 + wn2 + nj * 8 + cq;
#pragma unroll
            for (int mi = 0; mi < 4; mi++) {
                const int row = wm + mi * 16 + rq;
                *(float2*)(ob + (size_t)row * N_V + col) =
                    make_float2(acc2[mi][nj][0], acc2[mi][nj][1]);
                *(float2*)(ob + (size_t)(row + 8) * N_V + col) =
                    make_float2(acc2[mi][nj][2], acc2[mi][nj][3]);
            }
        }
        if (h == 0) __syncthreads();   // stage reuse guard across halves
    }
}

// ---------------------------------------------------------------------------
extern "C" void kernel_launch(void* const* d_in, const int* in_sizes, int n_in,
                              void* d_out, int out_size)
{
    const float* x  = (const float*)d_in[0];
    const float* Wq = (const float*)d_in[1];
    const float* bq = (const float*)d_in[2];
    const float* Wk = (const float*)d_in[3];
    const float* bk = (const float*)d_in[4];
    const float* Wv = (const float*)d_in[5];
    const float* bv = (const float*)d_in[6];
    float* out = (float*)d_out;

    conv_all<<<CONVX_BLOCKS + CONVW_BLOCKS, 256>>>(x, Wq, Wk, Wv);

    cudaFuncSetAttribute(gemm_mma, cudaFuncAttributeMaxDynamicSharedMemorySize,
                         GEMM_SMEM);
    gemm_mma<<<dim3(6, 1024), 256, GEMM_SMEM>>>(bq, bk, bv);

    cudaFuncSetAttribute(attn_tc, cudaFuncAttributeMaxDynamicSharedMemorySize,
                         ATTN_SMEM);
    attn_tc<<<BD, 256, ATTN_SMEM>>>(out);
}